// round 14
// baseline (speedup 1.0000x reference)
#include <cuda_runtime.h>
#include <cstdint>

#define TT 4096
#define CC 768
#define HH 12
#define DH 64

// k-dims are stored PERMUTED within 8-element groups: memory order 0,4,1,5,2,6,3,7.
// pos(k) = ((k&3)<<1) | ((k>>2)&1). Fragment pairs (q, q+4) land at (2q, 2q+1) -> LDS.64.
#define PERM8(k) (((k) & ~7) | ((((k) & 3) << 1) | (((k) >> 2) & 1)))

// ---------------- device scratch (allocation-free rule) ----------------
__device__ float g_xt [TT * CC];        // x, tf32, k-permuted
__device__ float g_q  [HH * TT * DH];   // [h][t][d'], pre-scaled by 0.125*log2e, tf32, d-permuted
__device__ float g_k  [HH * TT * DH];   // [h][t][d'], tf32, d-permuted
__device__ float g_vt [HH * DH * TT];   // [h][d'][t], tf32, d-rows permuted
__device__ float g_att[TT * CC];        // concat heads, tf32 (k'-positions match g_wot)
__device__ float g_wt [3 * CC * CC];    // qkv weights [j][k'], tf32, k-permuted
__device__ float g_wot[CC * CC];        // wo as [n][k'], tf32, k-permuted
// split-K attention partials (qb 8..31 -> scratch rows 0..3071 per head, up to 4 parts)
__device__ float g_po[4 * HH * 3072 * DH];   // unnormalized O per part
__device__ float g_pm[4 * HH * 3072];        // row max (log2 domain)
__device__ float g_pl[4 * HH * 3072];        // row sum

// ---------------- helpers ----------------
static __device__ __forceinline__ uint32_t smem_u32(const void* p) {
    uint32_t a;
    asm("{ .reg .u64 t; cvta.to.shared.u64 t, %1; cvt.u32.u64 %0, t; }" : "=r"(a) : "l"(p));
    return a;
}
static __device__ __forceinline__ uint32_t tf32r(float f) {
    uint32_t u; asm("cvt.rna.tf32.f32 %0, %1;" : "=r"(u) : "f"(f)); return u;
}
static __device__ __forceinline__ float ex2(float x) {
    float y; asm("ex2.approx.f32 %0, %1;" : "=f"(y) : "f"(x)); return y;
}
static __device__ __forceinline__ void mma8(float* d, const uint32_t* a, const uint32_t* b) {
    asm volatile(
        "mma.sync.aligned.m16n8k8.row.col.f32.tf32.tf32.f32 "
        "{%0,%1,%2,%3}, {%4,%5,%6,%7}, {%8,%9}, {%0,%1,%2,%3};"
        : "+f"(d[0]), "+f"(d[1]), "+f"(d[2]), "+f"(d[3])
        : "r"(a[0]), "r"(a[1]), "r"(a[2]), "r"(a[3]), "r"(b[0]), "r"(b[1]));
}
static __device__ __forceinline__ void cpa(uint32_t dst, const void* src) {
    asm volatile("cp.async.cg.shared.global [%0], [%1], 16;" :: "r"(dst), "l"(src));
}
static __device__ __forceinline__ void cp_commit() {
    asm volatile("cp.async.commit_group;" ::: "memory");
}
template <int N> static __device__ __forceinline__ void cp_wait() {
    asm volatile("cp.async.wait_group %0;" :: "n"(N) : "memory");
}
// ---- mbarrier ----
static __device__ __forceinline__ void mb_init(uint32_t a, uint32_t cnt) {
    asm volatile("mbarrier.init.shared.b64 [%0], %1;" :: "r"(a), "r"(cnt) : "memory");
}
static __device__ __forceinline__ void mb_arrive(uint32_t a) {
    asm volatile("{ .reg .b64 t; mbarrier.arrive.shared.b64 t, [%0]; }" :: "r"(a) : "memory");
}
// NOINC is load-bearing: default form pre-increments pending count -> deadlock (R9/R10).
static __device__ __forceinline__ void cp_mb_arrive_noinc(uint32_t a) {
    asm volatile("cp.async.mbarrier.arrive.noinc.shared.b64 [%0];" :: "r"(a) : "memory");
}
static __device__ __forceinline__ void mb_wait(uint32_t a, uint32_t parity) {
    asm volatile(
        "{\n\t.reg .pred P1;\n\t"
        "W_%=:\n\t"
        "mbarrier.try_wait.parity.shared::cta.b64 P1, [%0], %1, 0x989680;\n\t"
        "@P1 bra D_%=;\n\t"
        "bra W_%=;\n\t"
        "D_%=:\n\t}"
        :: "r"(a), "r"(parity) : "memory");
}

// ---------------- merged preprocessing (k-permuting producers) ----------------
// grid: [0,1536) cvt_x (8 floats/thread); [1536,1968) tr_head; [1968,2112) tr_wo
__global__ __launch_bounds__(256) void prep(
    const float* __restrict__ x,
    const float* __restrict__ wq, const float* __restrict__ wk,
    const float* __restrict__ wv, const float* __restrict__ wo)
{
    const int b = blockIdx.x;
    if (b < 1536) {
        const size_t i8 = ((size_t)b * 256 + threadIdx.x) * 8;
        float4 v0 = *(const float4*)(x + i8);
        float4 v1 = *(const float4*)(x + i8 + 4);
        uint4 o0, o1;   // permuted order: k0,k4,k1,k5 | k2,k6,k3,k7
        o0.x = tf32r(v0.x); o0.y = tf32r(v1.x); o0.z = tf32r(v0.y); o0.w = tf32r(v1.y);
        o1.x = tf32r(v0.z); o1.y = tf32r(v1.z); o1.z = tf32r(v0.w); o1.w = tf32r(v1.w);
        *(uint4*)(g_xt + i8) = o0;
        *(uint4*)(g_xt + i8 + 4) = o1;
        return;
    }
    __shared__ float t[64][65];
    if (b < 1968) {
        const int bb = b - 1536;
        const int sel = bb / 144, r = bb % 144;
        const int k0 = (r % 12) * 64, h = r / 12;
        const float* src = (sel == 0) ? wq : (sel == 1) ? wk : wv;
        const float* s = src + (size_t)h * CC * DH;
        #pragma unroll
        for (int i = 0; i < 16; i++) {
            int e = threadIdx.x + i * 256; int kr = e >> 6, d = e & 63;
            t[kr][d] = s[(size_t)(k0 + kr) * DH + d];
        }
        __syncthreads();
        const int j0 = sel * CC;
        #pragma unroll
        for (int i = 0; i < 16; i++) {
            int e = threadIdx.x + i * 256; int d = e >> 6, kr = e & 63;
            g_wt[(size_t)(j0 + h * DH + d) * CC + k0 + PERM8(kr)] = __uint_as_float(tf32r(t[kr][d]));
        }
    } else {
        const int r = b - 1968;
        const int c0 = (r % 12) * 64, n0 = (r / 12) * 64;
        #pragma unroll
        for (int i = 0; i < 16; i++) {
            int e = threadIdx.x + i * 256; int cr = e >> 6, n = e & 63;
            t[cr][n] = wo[(size_t)(c0 + cr) * CC + n0 + n];
        }
        __syncthreads();
        #pragma unroll
        for (int i = 0; i < 16; i++) {
            int e = threadIdx.x + i * 256; int n = e >> 6, cr = e & 63;
            g_wot[(size_t)(n0 + n) * CC + c0 + PERM8(cr)] = __uint_as_float(tf32r(t[cr][n]));
        }
    }
}

// ---------------- GEMM (tf32 mma.sync, 3-stage cp.async, LDS.64 frags) --------------
#define GBUF 4608              // 128*36 u32 per matrix
#define GBUFSZ 9216            // per stage (A+B)

template <int MODE>
__global__ __launch_bounds__(256, 2) void gemm_k(
    const float* __restrict__ Am, const float* __restrict__ Bm,
    const float* __restrict__ x0, const float* __restrict__ x1,
    const float* __restrict__ x2, float* __restrict__ outp)
{
    extern __shared__ uint32_t sm[];
    const uint32_t usm = smem_u32(sm);
    const int tid = threadIdx.x;
    const int warp = tid >> 5, lane = tid & 31;
    const int g = lane >> 2, q = lane & 3;
    const int warp_m = warp & 3, warp_n = warp >> 2;
    const int m0 = blockIdx.x * 128, n0 = blockIdx.y * 128;

    auto ldgsts = [&](int k0, int buf) {
        const uint32_t uA = usm + buf * GBUFSZ * 4;
        const uint32_t uB = uA + GBUF * 4;
        #pragma unroll
        for (int i = 0; i < 4; i++) {
            int idx = tid + i * 256; int r = idx >> 3, cc = idx & 7;
            cpa(uA + (r * 36 + cc * 4) * 4, Am + (size_t)(m0 + r) * CC + k0 + cc * 4);
            cpa(uB + (r * 36 + cc * 4) * 4, Bm + (size_t)(n0 + r) * CC + k0 + cc * 4);
        }
        cp_commit();
    };

    float Cf[2][8][4];
    #pragma unroll
    for (int tm = 0; tm < 2; tm++)
        #pragma unroll
        for (int tn = 0; tn < 8; tn++)
            #pragma unroll
            for (int k = 0; k < 4; k++) Cf[tm][tn][k] = 0.f;

    ldgsts(0, 0);
    ldgsts(32, 1);

    int buf = 0;
    for (int c = 0; c < 24; c++) {
        cp_wait<1>();
        __syncthreads();
        if (c < 22) ldgsts((c + 2) * 32, (c + 2) % 3);
        const uint32_t* sA = sm + buf * GBUFSZ;
        const uint32_t* sB = sA + GBUF;
        #pragma unroll
        for (int ks = 0; ks < 4; ks++) {
            uint32_t a[2][4];
            #pragma unroll
            for (int tm = 0; tm < 2; tm++) {
                int row = warp_m * 32 + tm * 16 + g;
                uint2 u0 = *(const uint2*)(sA + row * 36 + ks * 8 + 2 * q);
                uint2 u1 = *(const uint2*)(sA + (row + 8) * 36 + ks * 8 + 2 * q);
                a[tm][0] = u0.x; a[tm][2] = u0.y;
                a[tm][1] = u1.x; a[tm][3] = u1.y;
            }
            #pragma unroll
            for (int tn = 0; tn < 8; tn++) {
                int col = warp_n * 64 + tn * 8 + g;
                uint2 ub = *(const uint2*)(sB + col * 36 + ks * 8 + 2 * q);
                uint32_t b[2] = { ub.x, ub.y };
                mma8(Cf[0][tn], a[0], b);
                mma8(Cf[1][tn], a[1], b);
            }
        }
        buf = (buf + 1) % 3;
    }

    const int jb = n0 + warp_n * 64;
    // permuted positions for this thread's (2q, 2q+1) column pair within its 8-group
    const int p0 = (q & 1) * 4 + (q >> 1);   // pos(2q)
    const int p1 = p0 + 2;                   // pos(2q+1)
    if (MODE == 0) {
        const float c1 = 0.18033688011112042f;   // 0.125 * log2(e)
        const int sel = jb / CC, rem = jb % CC, h = rem >> 6;
        const float* bias = (sel == 0) ? x0 : (sel == 1) ? x1 : x2;
        #pragma unroll
        for (int tm = 0; tm < 2; tm++) {
            const int t0 = m0 + warp_m * 32 + tm * 16 + g;
            #pragma unroll
            for (int tn = 0; tn < 8; tn++) {
                const int d = tn * 8 + 2 * q;
                const float b0 = bias[h * DH + d], b1 = bias[h * DH + d + 1];
                float v00 = Cf[tm][tn][0] + b0, v01 = Cf[tm][tn][1] + b1;
                float v10 = Cf[tm][tn][2] + b0, v11 = Cf[tm][tn][3] + b1;
                const int d0 = tn * 8 + p0, d1 = tn * 8 + p1;   // permuted d positions
                if (sel == 0) {
                    float* dst = g_q + (size_t)h * TT * DH;
                    dst[(size_t)t0 * DH + d0]       = __uint_as_float(tf32r(v00 * c1));
                    dst[(size_t)t0 * DH + d1]       = __uint_as_float(tf32r(v01 * c1));
                    dst[(size_t)(t0 + 8) * DH + d0] = __uint_as_float(tf32r(v10 * c1));
                    dst[(size_t)(t0 + 8) * DH + d1] = __uint_as_float(tf32r(v11 * c1));
                } else if (sel == 1) {
                    float* dst = g_k + (size_t)h * TT * DH;
                    dst[(size_t)t0 * DH + d0]       = __uint_as_float(tf32r(v00));
                    dst[(size_t)t0 * DH + d1]       = __uint_as_float(tf32r(v01));
                    dst[(size_t)(t0 + 8) * DH + d0] = __uint_as_float(tf32r(v10));
                    dst[(size_t)(t0 + 8) * DH + d1] = __uint_as_float(tf32r(v11));
                } else {
                    float* dst = g_vt + (size_t)h * DH * TT;
                    dst[(size_t)d0 * TT + t0]     = __uint_as_float(tf32r(v00));
                    dst[(size_t)d1 * TT + t0]     = __uint_as_float(tf32r(v01));
                    dst[(size_t)d0 * TT + t0 + 8] = __uint_as_float(tf32r(v10));
                    dst[(size_t)d1 * TT + t0 + 8] = __uint_as_float(tf32r(v11));
                }
            }
        }
    } else {
        const float* bo = x0;
        #pragma unroll
        for (int tm = 0; tm < 2; tm++) {
            const int t0 = m0 + warp_m * 32 + tm * 16 + g;
            #pragma unroll
            for (int tn = 0; tn < 8; tn++) {
                const int j = jb + tn * 8 + 2 * q;
                const float b0 = bo[j], b1 = bo[j + 1];
                float2 v0 = { Cf[tm][tn][0] + b0, Cf[tm][tn][1] + b1 };
                float2 v1 = { Cf[tm][tn][2] + b0, Cf[tm][tn][3] + b1 };
                *(float2*)(outp + (size_t)t0 * CC + j) = v0;
                *(float2*)(outp + (size_t)(t0 + 8) * CC + j) = v1;
            }
        }
    }
}

// ---------------- flash attention (fine split-K + LDS.64 Q/K frags) ------------------
// grid.x = 80 per head (descending work), parts of <=16 key-blocks; see R13.
#define ABUF 4352   // 64*68

__global__ __launch_bounds__(128, 2) void attn()
{
    extern __shared__ uint32_t sm[];
    __shared__ __align__(8) unsigned long long mbar_s[4];  // full0, full1, empty0, empty1
    uint32_t* Ps = sm;
    const uint32_t uPs = smem_u32(sm);
    const uint32_t ubar = smem_u32(mbar_s);

    const int tid = threadIdx.x;
    const int warp = tid >> 5, lane = tid & 31;
    const int g = lane >> 2, q = lane & 3;
    const int h = blockIdx.y;
    const int rb = warp * 32;

    const int bx = blockIdx.x;
    int qb, part, np;
    if (bx < 32)      { qb = 31 - (bx >> 2);        part = bx & 3;        np = 4; }
    else if (bx < 56) { int t = bx - 32; qb = 23 - t / 3; part = t % 3;   np = 3; }
    else if (bx < 72) { int t = bx - 56; qb = 15 - (t >> 1); part = t & 1; np = 2; }
    else              { qb = 7 - (bx - 72);          part = 0;            np = 1; }
    const int W  = 2 * qb + 2;
    const int j0 = (W * part) / np;
    const int j1 = (W * (part + 1)) / np;
    const int nloc = j1 - j0;
    const bool split = (np > 1);

    const float* Qg = g_q  + (size_t)h * TT * DH + (size_t)qb * 128 * DH;
    const float* Kg = g_k  + (size_t)h * TT * DH;
    const float* Vg = g_vt + (size_t)h * DH * TT;

    if (tid == 0) {
        mb_init(ubar + 0, 128);   // full0
        mb_init(ubar + 8, 128);   // full1
        mb_init(ubar + 16, 4);    // empty0
        mb_init(ubar + 24, 4);    // empty1
    }

    auto load_kv = [&](int j, int buf) {
        const uint32_t uK = uPs + (8704 + buf * ABUF) * 4;
        const uint32_t uV = uPs + (17408 + buf * ABUF) * 4;
        #pragma unroll
        for (int i = 0; i < 8; i++) {
            int idx = tid + i * 128; int r = idx >> 4, cc = idx & 15;
            cpa(uK + (r * 68 + cc * 4) * 4, Kg + (size_t)(j * 64 + r) * DH + cc * 4);
            cpa(uV + (r * 68 + cc * 4) * 4, Vg + (size_t)r * TT + j * 64 + cc * 4);
        }
    };

    // prologue: stage Q into Ps, load first KV block (group wait + CTA barrier,
    // which also publishes the mbarrier inits)
    #pragma unroll
    for (int i = 0; i < 16; i++) {
        int idx = tid + i * 128; int r = idx >> 4, cc = idx & 15;
        cpa(uPs + (r * 68 + cc * 4) * 4, Qg + (size_t)r * DH + cc * 4);
    }
    load_kv(j0, 0);
    cp_commit();
    cp_wait<0>();
    __syncthreads();

    // Q fragments -> registers (d-permuted layout -> LDS.64 pairs)
    uint32_t A[2][8][4];
    #pragma unroll
    for (int tm = 0; tm < 2; tm++) {
        const int base = rb + tm * 16;
        #pragma unroll
        for (int ks = 0; ks < 8; ks++) {
            uint2 u0 = *(const uint2*)(Ps + (base + g) * 68 + ks * 8 + 2 * q);
            uint2 u1 = *(const uint2*)(Ps + (base + 8 + g) * 68 + ks * 8 + 2 * q);
            A[tm][ks][0] = u0.x; A[tm][ks][2] = u0.y;
            A[tm][ks][1] = u1.x; A[tm][ks][3] = u1.y;
        }
    }
    __syncwarp();   // Ps rows are warp-private from here on (P storage)

    float O[2][8][4];
    #pragma unroll
    for (int tm = 0; tm < 2; tm++)
        #pragma unroll
        for (int tn = 0; tn < 8; tn++)
            #pragma unroll
            for (int k = 0; k < 4; k++) O[tm][tn][k] = 0.f;
    float mv[4], lv[4];
    #pragma unroll
    for (int i = 0; i < 4; i++) { mv[i] = -1e30f; lv[i] = 0.f; }

    const int r0 = qb * 128 + rb + g;

    // per-warp parities: full start 0; empty0 starts 0, empty1 starts 1
    int pf0 = 0, pf1 = 0, pe0 = 0, pe1 = 1;

    for (int jj = 0; jj < nloc; jj++) {
        const int j = j0 + jj;
        const int b = jj & 1;
        if (jj) {
            if (b == 0) { mb_wait(ubar + 0, pf0); pf0 ^= 1; }
            else        { mb_wait(ubar + 8, pf1); pf1 ^= 1; }
        }
        if (jj + 1 < nloc) {
            const int nb = (jj + 1) & 1;
            if (nb == 0) { mb_wait(ubar + 16, pe0); pe0 ^= 1; }
            else         { mb_wait(ubar + 24, pe1); pe1 ^= 1; }
            load_kv(j + 1, nb);
            cp_mb_arrive_noinc(ubar + nb * 8);   // arm full[nb] (all 128 threads)
        }
        const uint32_t* Ks = sm + 8704 + b * ABUF;
        const uint32_t* Vs = sm + 17408 + b * ABUF;

        // S = Q @ K^T (log2 domain; Q pre-scaled; K d-permuted -> LDS.64 b-frags)
        float S[2][8][4];
        #pragma unroll
        for (int tm = 0; tm < 2; tm++)
            #pragma unroll
            for (int tn = 0; tn < 8; tn++)
                #pragma unroll
                for (int k = 0; k < 4; k++) S[tm][tn][k] = 0.f;
        #pragma unroll
        for (int ks = 0; ks < 8; ks++) {
            #pragma unroll
            for (int tn = 0; tn < 8; tn++) {
                uint2 ub = *(const uint2*)(Ks + (tn * 8 + g) * 68 + ks * 8 + 2 * q);
                uint32_t bb[2] = { ub.x, ub.y };
                mma8(S[0][tn], A[0][ks], bb);
                mma8(S[1][tn], A[1][ks], bb);
            }
        }

        // causal mask (diagonal key-blocks only; j is absolute)
        if (j >= 2 * qb) {
            const int kb = j * 64;
            #pragma unroll
            for (int tn = 0; tn < 8; tn++) {
                const int col = kb + tn * 8 + 2 * q;
                #pragma unroll
                for (int tm = 0; tm < 2; tm++) {
                    const int ra = r0 + tm * 16, rb2 = ra + 8;
                    if (col > ra)      S[tm][tn][0] = -1e30f;
                    if (col + 1 > ra)  S[tm][tn][1] = -1e30f;
                    if (col > rb2)     S[tm][tn][2] = -1e30f;
                    if (col + 1 > rb2) S[tm][tn][3] = -1e30f;
                }
            }
        }

        // online softmax over 4 rows
        float tmax[4] = { -1e30f, -1e30f, -1e30f, -1e30f };
        #pragma unroll
        for (int tm = 0; tm < 2; tm++)
            #pragma unroll
            for (int tn = 0; tn < 8; tn++) {
                tmax[tm * 2]     = fmaxf(tmax[tm * 2],     fmaxf(S[tm][tn][0], S[tm][tn][1]));
                tmax[tm * 2 + 1] = fmaxf(tmax[tm * 2 + 1], fmaxf(S[tm][tn][2], S[tm][tn][3]));
            }
        float al[4];
        #pragma unroll
        for (int i = 0; i < 4; i++) {
            tmax[i] = fmaxf(tmax[i], __shfl_xor_sync(0xffffffffu, tmax[i], 1));
            tmax[i] = fmaxf(tmax[i], __shfl_xor_sync(0xffffffffu, tmax[i], 2));
            const float mn = fmaxf(mv[i], tmax[i]);
            al[i] = ex2(mv[i] - mn);
            mv[i] = mn;
        }
        float rs[4] = { 0.f, 0.f, 0.f, 0.f };
        #pragma unroll
        for (int tm = 0; tm < 2; tm++)
            #pragma unroll
            for (int tn = 0; tn < 8; tn++) {
                S[tm][tn][0] = ex2(S[tm][tn][0] - mv[tm * 2]);
                S[tm][tn][1] = ex2(S[tm][tn][1] - mv[tm * 2]);
                S[tm][tn][2] = ex2(S[tm][tn][2] - mv[tm * 2 + 1]);
                S[tm][tn][3] = ex2(S[tm][tn][3] - mv[tm * 2 + 1]);
                rs[tm * 2]     += S[tm][tn][0] + S[tm][tn][1];
                rs[tm * 2 + 1] += S[tm][tn][2] + S[tm][tn][3];
            }
        #pragma unroll
        for (int i = 0; i < 4; i++) {
            rs[i] += __shfl_xor_sync(0xffffffffu, rs[i], 1);
            rs[i] += __shfl_xor_sync(0xffffffffu, rs[i], 2);
            lv[i] = lv[i] * al[i] + rs[i];
        }

        // P -> smem (warp-private rows; key-dim NOT permuted)
        #pragma unroll
        for (int tm = 0; tm < 2; tm++) {
            const int base = rb + tm * 16;
            #pragma unroll
            for (int tn = 0; tn < 8; tn++) {
                uint2 p0 = { tf32r(S[tm][tn][0]), tf32r(S[tm][tn][1]) };
                uint2 p1 = { tf32r(S[tm][tn][2]), tf32r(S[tm][tn][3]) };
                *(uint2*)(Ps + (base + g) * 68 + tn * 8 + 2 * q) = p0;
                *(uint2*)(Ps + (base + 8 + g) * 68 + tn * 8 + 2 * q) = p1;
            }
        }
        __syncwarp();

        // rescale O, accumulate P @ V
        #pragma unroll
        for (int tm = 0; tm < 2; tm++)
            #pragma unroll
            for (int tn = 0; tn < 8; tn++) {
                O[tm][tn][0] *= al[tm * 2];     O[tm][tn][1] *= al[tm * 2];
                O[tm][tn][2] *= al[tm * 2 + 1]; O[tm][tn][3] *= al[tm * 2 + 1];
            }
        #pragma unroll
        for (int ks = 0; ks < 8; ks++) {
            uint32_t a[2][4];
            #pragma unroll
            for (int tm = 0; tm < 2; tm++) {
                const int base = rb + tm * 16;
                a[tm][0] = Ps[(base + g) * 68 + ks * 8 + q];
                a[tm][1] = Ps[(base + 8 + g) * 68 + ks * 8 + q];
                a[tm][2] = Ps[(base + g) * 68 + ks * 8 + q + 4];
                a[tm][3] = Ps[(base + 8 + g) * 68 + ks * 8 + q + 4];
            }
            #pragma unroll
            for (int tn = 0; tn < 8; tn++) {
                uint32_t bb[2];
                bb[0] = Vs[(tn * 8 + g) * 68 + ks * 8 + q];
                bb[1] = Vs[(tn * 8 + g) * 68 + ks * 8 + q + 4];
                mma8(O[0][tn], a[0], bb);
                mma8(O[1][tn], a[1], bb);
            }
        }
        __syncwarp();
        if (lane == 0) mb_arrive(ubar + 16 + b * 8);   // release stage b
    }

    if (!split) {
        // unsplit: normalize and write g_att (cols already in permuted k'-order)
        #pragma unroll
        for (int tm = 0; tm < 2; tm++) {
            const int ra = r0 + tm * 16;
            const float i0 = 1.f / lv[tm * 2], i1 = 1.f / lv[tm * 2 + 1];
            #pragma unroll
            for (int tn = 0; tn < 8; tn++) {
                const int d = tn * 8 + 2 * q;
                uint2 v0 = { tf32r(O[tm][tn][0] * i0), tf32r(O[tm][tn][1] * i0) };
                uint2 v1 = { tf32r(O[tm][tn][2] * i1), tf32r(O[tm][tn][3] * i1) };
                *(uint2*)(g_att + (size_t)ra * CC + h * DH + d) = v0;
                *(uint2*)(g_att + (size_t)(ra + 8) * CC + h * DH + d) = v1;
            }
        }
    } else {
        // split: write unnormalized O + (m, l) to scratch (rows 0..3071 per head)
        const int sb = (qb - 8) * 128;
        float* poB = g_po + ((size_t)part * HH + h) * 3072 * 64;
        #pragma unroll
        for (int tm = 0; tm < 2; tm++) {
            const int lr = rb + tm * 16 + g;
            #pragma unroll
            for (int tn = 0; tn < 8; tn++) {
                const int d = tn * 8 + 2 * q;
                float2 v0 = { O[tm][tn][0], O[tm][tn][1] };
                float2 v1 = { O[tm][tn][2], O[tm][tn][3] };
                *(float2*)(poB + (size_t)(sb + lr) * 64 + d) = v0;
                *(float2*)(poB + (size_t)(sb + lr + 8) * 64 + d) = v1;
            }
            if (q == 0) {
                const size_t mi = ((size_t)part * HH + h) * 3072 + sb;
                g_pm[mi + lr]     = mv[tm * 2];     g_pl[mi + lr]     = lv[tm * 2];
                g_pm[mi + lr + 8] = mv[tm * 2 + 1]; g_pl[mi + lr + 8] = lv[tm * 2 + 1];
            }
        }
    }
}

// ---------------- merge split-K partials (element-wise over d -> perm-invariant) -----
__global__ __launch_bounds__(256) void merge_k()
{
    const int idx = blockIdx.x * 256 + threadIdx.x;   // 12 * 3072 * 16 = 589824
    const int d4  = (idx & 15) * 4;
    const int row = (idx >> 4) % 3072;
    const int h   = idx / (3072 * 16);

    const int qb = 8 + (row >> 7);
    const int np = (qb >= 24) ? 4 : (qb >= 16) ? 3 : 2;

    const size_t mi0 = (size_t)h * 3072 + row;
    float m = -1e30f;
    #pragma unroll
    for (int p = 0; p < 4; p++)
        if (p < np) m = fmaxf(m, g_pm[(size_t)p * HH * 3072 + mi0]);

    float den = 0.f;
    float4 acc = { 0.f, 0.f, 0.f, 0.f };
    #pragma unroll
    for (int p = 0; p < 4; p++) {
        if (p >= np) break;
        const size_t mi = (size_t)p * HH * 3072 + mi0;
        const float w = ex2(g_pm[mi] - m);
        den += g_pl[mi] * w;
        const float4 o = *(const float4*)(g_po + ((size_t)p * HH + h) * 3072 * 64
                                               + (size_t)row * 64 + d4);
        acc.x += o.x * w; acc.y += o.y * w; acc.z += o.z * w; acc.w += o.w * w;
    }
    const float inv = 1.f / den;
    uint4 r;
    r.x = tf32r(acc.x * inv); r.y = tf32r(acc.y * inv);
    r.z = tf32r(acc.z * inv); r.w = tf32r(acc.w * inv);

    const int tok = qb * 128 + (row & 127);
    *(uint4*)(g_att + (size_t)tok * CC + h * DH + d4) = r;
}

// ---------------- launcher ----------------
extern "C" void kernel_launch(void* const* d_in, const int* in_sizes, int n_in,
                              void* d_out, int out_size)
{
    const float* x  = (const float*)d_in[0];
    const float* wq = (const float*)d_in[1];
    const float* bq = (const float*)d_in[2];
    const float* wk = (const float*)d_in[3];
    const float* bk = (const float*)d_in[4];
    const float* wv = (const float*)d_in[5];
    const float* bv = (const float*)d_in[6];
    const float* wo = (const float*)d_in[7];
    const float* bo = (const float*)d_in[8];

    const int GSM = 3 * GBUFSZ * 4;    // 110592 B (3-stage)
    const int ASM = 26112 * 4;         // 104448 B
    cudaFuncSetAttribute(gemm_k<0>, cudaFuncAttributeMaxDynamicSharedMemorySize, GSM);
    cudaFuncSetAttribute(gemm_k<1>, cudaFuncAttributeMaxDynamicSharedMemorySize, GSM);
    cudaFuncSetAttribute(attn,      cudaFuncAttributeMaxDynamicSharedMemorySize, ASM);

    float* xt_dev;  cudaGetSymbolAddress((void**)&xt_dev,  g_xt);
    float* wt_dev;  cudaGetSymbolAddress((void**)&wt_dev,  g_wt);
    float* wot_dev; cudaGetSymbolAddress((void**)&wot_dev, g_wot);
    float* att_dev; cudaGetSymbolAddress((void**)&att_dev, g_att);

    prep<<<2112, 256>>>(x, wq, wk, wv, wo);
    gemm_k<0><<<dim3(32, 18), 256, GSM>>>(xt_dev, wt_dev, bq, bk, bv, nullptr);
    attn<<<dim3(80, 12), 128, ASM>>>();
    merge_k<<<2304, 256>>>();
    gemm_k<1><<<dim3(32, 6), 256, GSM>>>(att_dev, wot_dev, bo, nullptr, nullptr, (float*)d_out);
}

// round 15
// speedup vs baseline: 1.1257x; 1.1257x over previous
#include <cuda_runtime.h>
#include <cstdint>

#define TT 4096
#define CC 768
#define HH 12
#define DH 64

// ---------------- device scratch (allocation-free rule) ----------------
__device__ float g_xt [TT * CC];        // x, tf32-rounded
__device__ float g_q  [HH * TT * DH];   // [h][t][d], pre-scaled by 0.125*log2e, tf32
__device__ float g_k  [HH * TT * DH];   // [h][t][d], tf32
// V transposed [h][d][t], tf32, with t PERMUTED within 8-groups:
// slot p holds logical key 2p (p<4) / 2(p-4)+1 (p>=4)  <=>  key k stored at
// (k&~7) | ((k&1)*4 + ((k&7)>>1)). This makes S's C-fragment directly usable as
// the PV A-fragment (a = {c0,c2,c1,c3}) -- no P smem round-trip.
__device__ float g_vt [HH * DH * TT];
__device__ float g_att[TT * CC];        // concat heads, tf32
__device__ float g_wt [3 * CC * CC];    // qkv weights [j][k], tf32
__device__ float g_wot[CC * CC];        // wo as [n][k], tf32
// split-K attention partials (qb 8..31 -> scratch rows 0..3071 per head, up to 4 parts)
__device__ float g_po[4 * HH * 3072 * DH];   // unnormalized O per part
__device__ float g_pm[4 * HH * 3072];        // row max (log2 domain)
__device__ float g_pl[4 * HH * 3072];        // row sum

// ---------------- helpers ----------------
static __device__ __forceinline__ uint32_t smem_u32(const void* p) {
    uint32_t a;
    asm("{ .reg .u64 t; cvta.to.shared.u64 t, %1; cvt.u32.u64 %0, t; }" : "=r"(a) : "l"(p));
    return a;
}
static __device__ __forceinline__ uint32_t tf32r(float f) {
    uint32_t u; asm("cvt.rna.tf32.f32 %0, %1;" : "=r"(u) : "f"(f)); return u;
}
static __device__ __forceinline__ float ex2(float x) {
    float y; asm("ex2.approx.f32 %0, %1;" : "=f"(y) : "f"(x)); return y;
}
static __device__ __forceinline__ void mma8(float* d, const uint32_t* a, const uint32_t* b) {
    asm volatile(
        "mma.sync.aligned.m16n8k8.row.col.f32.tf32.tf32.f32 "
        "{%0,%1,%2,%3}, {%4,%5,%6,%7}, {%8,%9}, {%0,%1,%2,%3};"
        : "+f"(d[0]), "+f"(d[1]), "+f"(d[2]), "+f"(d[3])
        : "r"(a[0]), "r"(a[1]), "r"(a[2]), "r"(a[3]), "r"(b[0]), "r"(b[1]));
}
static __device__ __forceinline__ uint4 cvt4(float4 v) {
    uint4 t; t.x = tf32r(v.x); t.y = tf32r(v.y); t.z = tf32r(v.z); t.w = tf32r(v.w);
    return t;
}
static __device__ __forceinline__ void cpa(uint32_t dst, const void* src) {
    asm volatile("cp.async.cg.shared.global [%0], [%1], 16;" :: "r"(dst), "l"(src));
}
static __device__ __forceinline__ void cp_commit() {
    asm volatile("cp.async.commit_group;" ::: "memory");
}
template <int N> static __device__ __forceinline__ void cp_wait() {
    asm volatile("cp.async.wait_group %0;" :: "n"(N) : "memory");
}
// ---- mbarrier ----
static __device__ __forceinline__ void mb_init(uint32_t a, uint32_t cnt) {
    asm volatile("mbarrier.init.shared.b64 [%0], %1;" :: "r"(a), "r"(cnt) : "memory");
}
static __device__ __forceinline__ void mb_arrive(uint32_t a) {
    asm volatile("{ .reg .b64 t; mbarrier.arrive.shared.b64 t, [%0]; }" :: "r"(a) : "memory");
}
// NOINC is load-bearing: default form pre-increments pending count -> deadlock (R9/R10).
static __device__ __forceinline__ void cp_mb_arrive_noinc(uint32_t a) {
    asm volatile("cp.async.mbarrier.arrive.noinc.shared.b64 [%0];" :: "r"(a) : "memory");
}
static __device__ __forceinline__ void mb_wait(uint32_t a, uint32_t parity) {
    asm volatile(
        "{\n\t.reg .pred P1;\n\t"
        "W_%=:\n\t"
        "mbarrier.try_wait.parity.shared::cta.b64 P1, [%0], %1, 0x989680;\n\t"
        "@P1 bra D_%=;\n\t"
        "bra W_%=;\n\t"
        "D_%=:\n\t}"
        :: "r"(a), "r"(parity) : "memory");
}

// ---------------- merged preprocessing: cvt_x + 3x tr_head + tr_wo ----------------
__global__ __launch_bounds__(256) void prep(
    const float* __restrict__ x,
    const float* __restrict__ wq, const float* __restrict__ wk,
    const float* __restrict__ wv, const float* __restrict__ wo)
{
    const int b = blockIdx.x;
    if (b < 3072) {
        int i = b * 256 + threadIdx.x;
        float4 v = ((const float4*)x)[i];
        ((uint4*)g_xt)[i] = cvt4(v);
        return;
    }
    __shared__ float t[64][65];
    if (b < 3504) {
        const int bb = b - 3072;
        const int sel = bb / 144, r = bb % 144;
        const int k0 = (r % 12) * 64, h = r / 12;
        const float* src = (sel == 0) ? wq : (sel == 1) ? wk : wv;
        const float* s = src + (size_t)h * CC * DH;
        #pragma unroll
        for (int i = 0; i < 16; i++) {
            int e = threadIdx.x + i * 256; int kr = e >> 6, d = e & 63;
            t[kr][d] = s[(size_t)(k0 + kr) * DH + d];
        }
        __syncthreads();
        const int j0 = sel * CC;
        #pragma unroll
        for (int i = 0; i < 16; i++) {
            int e = threadIdx.x + i * 256; int d = e >> 6, kr = e & 63;
            g_wt[(size_t)(j0 + h * DH + d) * CC + k0 + kr] = __uint_as_float(tf32r(t[kr][d]));
        }
    } else {
        const int r = b - 3504;
        const int c0 = (r % 12) * 64, n0 = (r / 12) * 64;
        #pragma unroll
        for (int i = 0; i < 16; i++) {
            int e = threadIdx.x + i * 256; int cr = e >> 6, n = e & 63;
            t[cr][n] = wo[(size_t)(c0 + cr) * CC + n0 + n];
        }
        __syncthreads();
        #pragma unroll
        for (int i = 0; i < 16; i++) {
            int e = threadIdx.x + i * 256; int n = e >> 6, cr = e & 63;
            g_wot[(size_t)(n0 + n) * CC + c0 + cr] = __uint_as_float(tf32r(t[cr][n]));
        }
    }
}

// ---------------- GEMM (tf32 mma.sync, 3-stage cp.async): MODE 0 = qkv, 1 = out -----
#define GBUF 4608              // 128*36 u32 per matrix
#define GBUFSZ 9216            // per stage (A+B)

template <int MODE>
__global__ __launch_bounds__(256, 2) void gemm_k(
    const float* __restrict__ Am, const float* __restrict__ Bm,
    const float* __restrict__ x0, const float* __restrict__ x1,
    const float* __restrict__ x2, float* __restrict__ outp)
{
    extern __shared__ uint32_t sm[];
    const uint32_t usm = smem_u32(sm);
    const int tid = threadIdx.x;
    const int warp = tid >> 5, lane = tid & 31;
    const int g = lane >> 2, q = lane & 3;
    const int warp_m = warp & 3, warp_n = warp >> 2;
    const int m0 = blockIdx.x * 128, n0 = blockIdx.y * 128;

    auto ldgsts = [&](int k0, int buf) {
        const uint32_t uA = usm + buf * GBUFSZ * 4;
        const uint32_t uB = uA + GBUF * 4;
        #pragma unroll
        for (int i = 0; i < 4; i++) {
            int idx = tid + i * 256; int r = idx >> 3, cc = idx & 7;
            cpa(uA + (r * 36 + cc * 4) * 4, Am + (size_t)(m0 + r) * CC + k0 + cc * 4);
            cpa(uB + (r * 36 + cc * 4) * 4, Bm + (size_t)(n0 + r) * CC + k0 + cc * 4);
        }
        cp_commit();
    };

    float Cf[2][8][4];
    #pragma unroll
    for (int tm = 0; tm < 2; tm++)
        #pragma unroll
        for (int tn = 0; tn < 8; tn++)
            #pragma unroll
            for (int k = 0; k < 4; k++) Cf[tm][tn][k] = 0.f;

    ldgsts(0, 0);
    ldgsts(32, 1);

    int buf = 0;
    for (int c = 0; c < 24; c++) {
        cp_wait<1>();
        __syncthreads();
        if (c < 22) ldgsts((c + 2) * 32, (c + 2) % 3);
        const uint32_t* sA = sm + buf * GBUFSZ;
        const uint32_t* sB = sA + GBUF;
        #pragma unroll
        for (int ks = 0; ks < 4; ks++) {
            uint32_t a[2][4];
            #pragma unroll
            for (int tm = 0; tm < 2; tm++) {
                int row = warp_m * 32 + tm * 16 + g;
                a[tm][0] = sA[row * 36 + ks * 8 + q];
                a[tm][1] = sA[(row + 8) * 36 + ks * 8 + q];
                a[tm][2] = sA[row * 36 + ks * 8 + q + 4];
                a[tm][3] = sA[(row + 8) * 36 + ks * 8 + q + 4];
            }
            #pragma unroll
            for (int tn = 0; tn < 8; tn++) {
                uint32_t b[2];
                int col = warp_n * 64 + tn * 8 + g;
                b[0] = sB[col * 36 + ks * 8 + q];
                b[1] = sB[col * 36 + ks * 8 + q + 4];
                mma8(Cf[0][tn], a[0], b);
                mma8(Cf[1][tn], a[1], b);
            }
        }
        buf = (buf + 1) % 3;
    }

    const int jb = n0 + warp_n * 64;
    if (MODE == 0) {
        const float c1 = 0.18033688011112042f;   // 0.125 * log2(e)
        const int sel = jb / CC, rem = jb % CC, h = rem >> 6;
        const float* bias = (sel == 0) ? x0 : (sel == 1) ? x1 : x2;
        // V key-permutation: row t -> (t & ~7) | ((t&1)*4 + ((t&7)>>1)); low 3 bits of
        // this thread's rows are exactly g.
        const int gp = (g & 1) * 4 + (g >> 1);
        #pragma unroll
        for (int tm = 0; tm < 2; tm++) {
            const int t0 = m0 + warp_m * 32 + tm * 16 + g;
            const int t0p = (t0 - g) + gp;     // permuted row for V
            #pragma unroll
            for (int tn = 0; tn < 8; tn++) {
                const int d = tn * 8 + 2 * q;
                const float b0 = bias[h * DH + d], b1 = bias[h * DH + d + 1];
                float v00 = Cf[tm][tn][0] + b0, v01 = Cf[tm][tn][1] + b1;
                float v10 = Cf[tm][tn][2] + b0, v11 = Cf[tm][tn][3] + b1;
                if (sel == 0) {
                    float* dst = g_q + (size_t)h * TT * DH;
                    uint2 p0 = { tf32r(v00 * c1), tf32r(v01 * c1) };
                    uint2 p1 = { tf32r(v10 * c1), tf32r(v11 * c1) };
                    *(uint2*)(dst + (size_t)t0 * DH + d) = p0;
                    *(uint2*)(dst + (size_t)(t0 + 8) * DH + d) = p1;
                } else if (sel == 1) {
                    float* dst = g_k + (size_t)h * TT * DH;
                    uint2 p0 = { tf32r(v00), tf32r(v01) };
                    uint2 p1 = { tf32r(v10), tf32r(v11) };
                    *(uint2*)(dst + (size_t)t0 * DH + d) = p0;
                    *(uint2*)(dst + (size_t)(t0 + 8) * DH + d) = p1;
                } else {
                    float* dst = g_vt + (size_t)h * DH * TT;
                    dst[(size_t)d * TT + t0p]           = __uint_as_float(tf32r(v00));
                    dst[(size_t)(d + 1) * TT + t0p]     = __uint_as_float(tf32r(v01));
                    dst[(size_t)d * TT + t0p + 8]       = __uint_as_float(tf32r(v10));
                    dst[(size_t)(d + 1) * TT + t0p + 8] = __uint_as_float(tf32r(v11));
                }
            }
        }
    } else {
        const float* bo = x0;
        #pragma unroll
        for (int tm = 0; tm < 2; tm++) {
            const int t0 = m0 + warp_m * 32 + tm * 16 + g;
            #pragma unroll
            for (int tn = 0; tn < 8; tn++) {
                const int j = jb + tn * 8 + 2 * q;
                const float b0 = bo[j], b1 = bo[j + 1];
                float2 v0 = { Cf[tm][tn][0] + b0, Cf[tm][tn][1] + b1 };
                float2 v1 = { Cf[tm][tn][2] + b0, Cf[tm][tn][3] + b1 };
                *(float2*)(outp + (size_t)t0 * CC + j) = v0;
                *(float2*)(outp + (size_t)(t0 + 8) * CC + j) = v1;
            }
        }
    }
}

// ---------------- flash attention (fine split-K + register-direct P feed) ------------
// grid.x = 80 per head (descending work), parts of <=16 key-blocks (see R13).
// PV's A-fragment is built from S's C-fragment registers (a = {c0,c2,c1,c3});
// V's key-slots are pre-permuted in g_vt so the k-interpretation matches.
#define ABUF 4352   // 64*68

__global__ __launch_bounds__(128, 2) void attn()
{
    extern __shared__ uint32_t sm[];
    __shared__ __align__(8) unsigned long long mbar_s[4];  // full0, full1, empty0, empty1
    uint32_t* Ps = sm;                 // Q staging only
    const uint32_t uPs = smem_u32(sm);
    const uint32_t ubar = smem_u32(mbar_s);

    const int tid = threadIdx.x;
    const int warp = tid >> 5, lane = tid & 31;
    const int g = lane >> 2, q = lane & 3;
    const int h = blockIdx.y;
    const int rb = warp * 32;

    const int bx = blockIdx.x;
    int qb, part, np;
    if (bx < 32)      { qb = 31 - (bx >> 2);        part = bx & 3;        np = 4; }
    else if (bx < 56) { int t = bx - 32; qb = 23 - t / 3; part = t % 3;   np = 3; }
    else if (bx < 72) { int t = bx - 56; qb = 15 - (t >> 1); part = t & 1; np = 2; }
    else              { qb = 7 - (bx - 72);          part = 0;            np = 1; }
    const int W  = 2 * qb + 2;
    const int j0 = (W * part) / np;
    const int j1 = (W * (part + 1)) / np;
    const int nloc = j1 - j0;
    const bool split = (np > 1);

    const float* Qg = g_q  + (size_t)h * TT * DH + (size_t)qb * 128 * DH;
    const float* Kg = g_k  + (size_t)h * TT * DH;
    const float* Vg = g_vt + (size_t)h * DH * TT;

    if (tid == 0) {
        mb_init(ubar + 0, 128);   // full0
        mb_init(ubar + 8, 128);   // full1
        mb_init(ubar + 16, 4);    // empty0
        mb_init(ubar + 24, 4);    // empty1
    }

    auto load_kv = [&](int j, int buf) {
        const uint32_t uK = uPs + (8704 + buf * ABUF) * 4;
        const uint32_t uV = uPs + (17408 + buf * ABUF) * 4;
        #pragma unroll
        for (int i = 0; i < 8; i++) {
            int idx = tid + i * 128; int r = idx >> 4, cc = idx & 15;
            cpa(uK + (r * 68 + cc * 4) * 4, Kg + (size_t)(j * 64 + r) * DH + cc * 4);
            cpa(uV + (r * 68 + cc * 4) * 4, Vg + (size_t)r * TT + j * 64 + cc * 4);
        }
    };

    // prologue: stage Q into Ps, load first KV block (group wait + CTA barrier,
    // which also publishes the mbarrier inits)
    #pragma unroll
    for (int i = 0; i < 16; i++) {
        int idx = tid + i * 128; int r = idx >> 4, cc = idx & 15;
        cpa(uPs + (r * 68 + cc * 4) * 4, Qg + (size_t)r * DH + cc * 4);
    }
    load_kv(j0, 0);
    cp_commit();
    cp_wait<0>();
    __syncthreads();

    // Q fragments -> registers (warp-private rows)
    uint32_t A[2][8][4];
    #pragma unroll
    for (int tm = 0; tm < 2; tm++) {
        const int base = rb + tm * 16;
        #pragma unroll
        for (int ks = 0; ks < 8; ks++) {
            A[tm][ks][0] = Ps[(base + g) * 68 + ks * 8 + q];
            A[tm][ks][1] = Ps[(base + 8 + g) * 68 + ks * 8 + q];
            A[tm][ks][2] = Ps[(base + g) * 68 + ks * 8 + q + 4];
            A[tm][ks][3] = Ps[(base + 8 + g) * 68 + ks * 8 + q + 4];
        }
    }

    float O[2][8][4];
    #pragma unroll
    for (int tm = 0; tm < 2; tm++)
        #pragma unroll
        for (int tn = 0; tn < 8; tn++)
            #pragma unroll
            for (int k = 0; k < 4; k++) O[tm][tn][k] = 0.f;
    float mv[4], lv[4];
    #pragma unroll
    for (int i = 0; i < 4; i++) { mv[i] = -1e30f; lv[i] = 0.f; }

    const int r0 = qb * 128 + rb + g;

    // per-warp parities: full start 0; empty0 starts 0, empty1 starts 1
    int pf0 = 0, pf1 = 0, pe0 = 0, pe1 = 1;

    for (int jj = 0; jj < nloc; jj++) {
        const int j = j0 + jj;
        const int b = jj & 1;
        if (jj) {
            if (b == 0) { mb_wait(ubar + 0, pf0); pf0 ^= 1; }
            else        { mb_wait(ubar + 8, pf1); pf1 ^= 1; }
        }
        if (jj + 1 < nloc) {
            const int nb = (jj + 1) & 1;
            if (nb == 0) { mb_wait(ubar + 16, pe0); pe0 ^= 1; }
            else         { mb_wait(ubar + 24, pe1); pe1 ^= 1; }
            load_kv(j + 1, nb);
            cp_mb_arrive_noinc(ubar + nb * 8);   // arm full[nb] (all 128 threads)
        }
        const uint32_t* Ks = sm + 8704 + b * ABUF;
        const uint32_t* Vs = sm + 17408 + b * ABUF;

        // S = Q @ K^T (log2 domain; Q pre-scaled)
        float S[2][8][4];
        #pragma unroll
        for (int tm = 0; tm < 2; tm++)
            #pragma unroll
            for (int tn = 0; tn < 8; tn++)
                #pragma unroll
                for (int k = 0; k < 4; k++) S[tm][tn][k] = 0.f;
        #pragma unroll
        for (int ks = 0; ks < 8; ks++) {
            #pragma unroll
            for (int tn = 0; tn < 8; tn++) {
                uint32_t bb[2];
                bb[0] = Ks[(tn * 8 + g) * 68 + ks * 8 + q];
                bb[1] = Ks[(tn * 8 + g) * 68 + ks * 8 + q + 4];
                mma8(S[0][tn], A[0][ks], bb);
                mma8(S[1][tn], A[1][ks], bb);
            }
        }

        // causal mask (diagonal key-blocks only; j is absolute; cols = logical keys)
        if (j >= 2 * qb) {
            const int kb = j * 64;
            #pragma unroll
            for (int tn = 0; tn < 8; tn++) {
                const int col = kb + tn * 8 + 2 * q;
                #pragma unroll
                for (int tm = 0; tm < 2; tm++) {
                    const int ra = r0 + tm * 16, rb2 = ra + 8;
                    if (col > ra)      S[tm][tn][0] = -1e30f;
                    if (col + 1 > ra)  S[tm][tn][1] = -1e30f;
                    if (col > rb2)     S[tm][tn][2] = -1e30f;
                    if (col + 1 > rb2) S[tm][tn][3] = -1e30f;
                }
            }
        }

        // online softmax over 4 rows
        float tmax[4] = { -1e30f, -1e30f, -1e30f, -1e30f };
        #pragma unroll
        for (int tm = 0; tm < 2; tm++)
            #pragma unroll
            for (int tn = 0; tn < 8; tn++) {
                tmax[tm * 2]     = fmaxf(tmax[tm * 2],     fmaxf(S[tm][tn][0], S[tm][tn][1]));
                tmax[tm * 2 + 1] = fmaxf(tmax[tm * 2 + 1], fmaxf(S[tm][tn][2], S[tm][tn][3]));
            }
        float al[4];
        #pragma unroll
        for (int i = 0; i < 4; i++) {
            tmax[i] = fmaxf(tmax[i], __shfl_xor_sync(0xffffffffu, tmax[i], 1));
            tmax[i] = fmaxf(tmax[i], __shfl_xor_sync(0xffffffffu, tmax[i], 2));
            const float mn = fmaxf(mv[i], tmax[i]);
            al[i] = ex2(mv[i] - mn);
            mv[i] = mn;
        }
        float rs[4] = { 0.f, 0.f, 0.f, 0.f };
        #pragma unroll
        for (int tm = 0; tm < 2; tm++)
            #pragma unroll
            for (int tn = 0; tn < 8; tn++) {
                S[tm][tn][0] = ex2(S[tm][tn][0] - mv[tm * 2]);
                S[tm][tn][1] = ex2(S[tm][tn][1] - mv[tm * 2]);
                S[tm][tn][2] = ex2(S[tm][tn][2] - mv[tm * 2 + 1]);
                S[tm][tn][3] = ex2(S[tm][tn][3] - mv[tm * 2 + 1]);
                rs[tm * 2]     += S[tm][tn][0] + S[tm][tn][1];
                rs[tm * 2 + 1] += S[tm][tn][2] + S[tm][tn][3];
            }
        #pragma unroll
        for (int i = 0; i < 4; i++) {
            rs[i] += __shfl_xor_sync(0xffffffffu, rs[i], 1);
            rs[i] += __shfl_xor_sync(0xffffffffu, rs[i], 2);
            lv[i] = lv[i] * al[i] + rs[i];
        }

        // rescale O, accumulate P @ V directly from S registers
        // (A-fragment = {c0, c2, c1, c3}; V key-slots pre-permuted to match)
        #pragma unroll
        for (int tm = 0; tm < 2; tm++)
            #pragma unroll
            for (int tn = 0; tn < 8; tn++) {
                O[tm][tn][0] *= al[tm * 2];     O[tm][tn][1] *= al[tm * 2];
                O[tm][tn][2] *= al[tm * 2 + 1]; O[tm][tn][3] *= al[tm * 2 + 1];
            }
        #pragma unroll
        for (int ks = 0; ks < 8; ks++) {
            uint32_t a[2][4];
            #pragma unroll
            for (int tm = 0; tm < 2; tm++) {
                a[tm][0] = tf32r(S[tm][ks][0]);
                a[tm][1] = tf32r(S[tm][ks][2]);
                a[tm][2] = tf32r(S[tm][ks][1]);
                a[tm][3] = tf32r(S[tm][ks][3]);
            }
            #pragma unroll
            for (int tn = 0; tn < 8; tn++) {
                uint32_t bb[2];
                bb[0] = Vs[(tn * 8 + g) * 68 + ks * 8 + q];
                bb[1] = Vs[(tn * 8 + g) * 68 + ks * 8 + q + 4];
                mma8(O[0][tn], a[0], bb);
                mma8(O[1][tn], a[1], bb);
            }
        }
        if (lane == 0) mb_arrive(ubar + 16 + b * 8);   // release stage b
    }

    if (!split) {
        // unsplit: normalize and write g_att (tf32-rounded for the out GEMM)
        #pragma unroll
        for (int tm = 0; tm < 2; tm++) {
            const int ra = r0 + tm * 16;
            const float i0 = 1.f / lv[tm * 2], i1 = 1.f / lv[tm * 2 + 1];
            #pragma unroll
            for (int tn = 0; tn < 8; tn++) {
                const int d = tn * 8 + 2 * q;
                uint2 v0 = { tf32r(O[tm][tn][0] * i0), tf32r(O[tm][tn][1] * i0) };
                uint2 v1 = { tf32r(O[tm][tn][2] * i1), tf32r(O[tm][tn][3] * i1) };
                *(uint2*)(g_att + (size_t)ra * CC + h * DH + d) = v0;
                *(uint2*)(g_att + (size_t)(ra + 8) * CC + h * DH + d) = v1;
            }
        }
    } else {
        // split: write unnormalized O + (m, l) to scratch (rows 0..3071 per head)
        const int sb = (qb - 8) * 128;
        float* poB = g_po + ((size_t)part * HH + h) * 3072 * 64;
        #pragma unroll
        for (int tm = 0; tm < 2; tm++) {
            const int lr = rb + tm * 16 + g;
            #pragma unroll
            for (int tn = 0; tn < 8; tn++) {
                const int d = tn * 8 + 2 * q;
                float2 v0 = { O[tm][tn][0], O[tm][tn][1] };
                float2 v1 = { O[tm][tn][2], O[tm][tn][3] };
                *(float2*)(poB + (size_t)(sb + lr) * 64 + d) = v0;
                *(float2*)(poB + (size_t)(sb + lr + 8) * 64 + d) = v1;
            }
            if (q == 0) {
                const size_t mi = ((size_t)part * HH + h) * 3072 + sb;
                g_pm[mi + lr]     = mv[tm * 2];     g_pl[mi + lr]     = lv[tm * 2];
                g_pm[mi + lr + 8] = mv[tm * 2 + 1]; g_pl[mi + lr + 8] = lv[tm * 2 + 1];
            }
        }
    }
}

// ---------------- merge split-K partials (token rows 1024..4095, 2-4 parts) ----------
__global__ __launch_bounds__(256) void merge_k()
{
    const int idx = blockIdx.x * 256 + threadIdx.x;   // 12 * 3072 * 16 = 589824
    const int d4  = (idx & 15) * 4;
    const int row = (idx >> 4) % 3072;
    const int h   = idx / (3072 * 16);

    const int qb = 8 + (row >> 7);
    const int np = (qb >= 24) ? 4 : (qb >= 16) ? 3 : 2;

    const size_t mi0 = (size_t)h * 3072 + row;
    float m = -1e30f;
    #pragma unroll
    for (int p = 0; p < 4; p++)
        if (p < np) m = fmaxf(m, g_pm[(size_t)p * HH * 3072 + mi0]);

    float den = 0.f;
    float4 acc = { 0.f, 0.f, 0.f, 0.f };
    #pragma unroll
    for (int p = 0; p < 4; p++) {
        if (p >= np) break;
        const size_t mi = (size_t)p * HH * 3072 + mi0;
        const float w = ex2(g_pm[mi] - m);
        den += g_pl[mi] * w;
        const float4 o = *(const float4*)(g_po + ((size_t)p * HH + h) * 3072 * 64
                                               + (size_t)row * 64 + d4);
        acc.x += o.x * w; acc.y += o.y * w; acc.z += o.z * w; acc.w += o.w * w;
    }
    const float inv = 1.f / den;
    uint4 r;
    r.x = tf32r(acc.x * inv); r.y = tf32r(acc.y * inv);
    r.z = tf32r(acc.z * inv); r.w = tf32r(acc.w * inv);

    const int tok = qb * 128 + (row & 127);
    *(uint4*)(g_att + (size_t)tok * CC + h * DH + d4) = r;
}

// ---------------- launcher ----------------
extern "C" void kernel_launch(void* const* d_in, const int* in_sizes, int n_in,
                              void* d_out, int out_size)
{
    const float* x  = (const float*)d_in[0];
    const float* wq = (const float*)d_in[1];
    const float* bq = (const float*)d_in[2];
    const float* wk = (const float*)d_in[3];
    const float* bk = (const float*)d_in[4];
    const float* wv = (const float*)d_in[5];
    const float* bv = (const float*)d_in[6];
    const float* wo = (const float*)d_in[7];
    const float* bo = (const float*)d_in[8];

    const int GSM = 3 * GBUFSZ * 4;    // 110592 B (3-stage)
    const int ASM = 26112 * 4;         // 104448 B
    cudaFuncSetAttribute(gemm_k<0>, cudaFuncAttributeMaxDynamicSharedMemorySize, GSM);
    cudaFuncSetAttribute(gemm_k<1>, cudaFuncAttributeMaxDynamicSharedMemorySize, GSM);
    cudaFuncSetAttribute(attn,      cudaFuncAttributeMaxDynamicSharedMemorySize, ASM);

    float* xt_dev;  cudaGetSymbolAddress((void**)&xt_dev,  g_xt);
    float* wt_dev;  cudaGetSymbolAddress((void**)&wt_dev,  g_wt);
    float* wot_dev; cudaGetSymbolAddress((void**)&wot_dev, g_wot);
    float* att_dev; cudaGetSymbolAddress((void**)&att_dev, g_att);

    prep<<<3648, 256>>>(x, wq, wk, wv, wo);
    gemm_k<0><<<dim3(32, 18), 256, GSM>>>(xt_dev, wt_dev, bq, bk, bv, nullptr);
    attn<<<dim3(80, 12), 128, ASM>>>();
    merge_k<<<2304, 256>>>();
    gemm_k<1><<<dim3(32, 6), 256, GSM>>>(att_dev, wot_dev, bo, nullptr, nullptr, (float*)d_out);
}

// round 16
// speedup vs baseline: 1.1453x; 1.0174x over previous
#include <cuda_runtime.h>
#include <cstdint>

#define TT 4096
#define CC 768
#define HH 12
#define DH 64

// ---------------- device scratch (allocation-free rule) ----------------
__device__ float g_xt [TT * CC];        // x, tf32-rounded
__device__ float g_q  [HH * TT * DH];   // [h][t][d], pre-scaled by 0.125*log2e, tf32
__device__ float g_k  [HH * TT * DH];   // [h][t][d], tf32
// V transposed [h][d][t], tf32, with t PERMUTED within 8-groups:
// slot p holds logical key 2p (p<4) / 2(p-4)+1 (p>=4)  <=>  key k stored at
// (k&~7) | ((k&1)*4 + ((k&7)>>1)). This makes S's C-fragment directly usable as
// the PV A-fragment (a = {c0,c2,c1,c3}) -- no P smem round-trip.
__device__ float g_vt [HH * DH * TT];
__device__ float g_att[TT * CC];        // concat heads, tf32
__device__ float g_wt [3 * CC * CC];    // qkv weights [j][k], tf32
__device__ float g_wot[CC * CC];        // wo as [n][k], tf32
// split-K attention partials (qb 8..31 -> scratch rows 0..3071 per head, up to 4 parts)
__device__ float g_po[4 * HH * 3072 * DH];   // unnormalized O per part
__device__ float g_pm[4 * HH * 3072];        // row max (log2 domain)
__device__ float g_pl[4 * HH * 3072];        // row sum

// ---------------- helpers ----------------
static __device__ __forceinline__ uint32_t smem_u32(const void* p) {
    uint32_t a;
    asm("{ .reg .u64 t; cvta.to.shared.u64 t, %1; cvt.u32.u64 %0, t; }" : "=r"(a) : "l"(p));
    return a;
}
static __device__ __forceinline__ uint32_t tf32r(float f) {
    uint32_t u; asm("cvt.rna.tf32.f32 %0, %1;" : "=r"(u) : "f"(f)); return u;
}
static __device__ __forceinline__ float ex2(float x) {
    float y; asm("ex2.approx.f32 %0, %1;" : "=f"(y) : "f"(x)); return y;
}
static __device__ __forceinline__ void mma8(float* d, const uint32_t* a, const uint32_t* b) {
    asm volatile(
        "mma.sync.aligned.m16n8k8.row.col.f32.tf32.tf32.f32 "
        "{%0,%1,%2,%3}, {%4,%5,%6,%7}, {%8,%9}, {%0,%1,%2,%3};"
        : "+f"(d[0]), "+f"(d[1]), "+f"(d[2]), "+f"(d[3])
        : "r"(a[0]), "r"(a[1]), "r"(a[2]), "r"(a[3]), "r"(b[0]), "r"(b[1]));
}
static __device__ __forceinline__ uint4 cvt4(float4 v) {
    uint4 t; t.x = tf32r(v.x); t.y = tf32r(v.y); t.z = tf32r(v.z); t.w = tf32r(v.w);
    return t;
}
static __device__ __forceinline__ void cpa(uint32_t dst, const void* src) {
    asm volatile("cp.async.cg.shared.global [%0], [%1], 16;" :: "r"(dst), "l"(src));
}
static __device__ __forceinline__ void cp_commit() {
    asm volatile("cp.async.commit_group;" ::: "memory");
}
template <int N> static __device__ __forceinline__ void cp_wait() {
    asm volatile("cp.async.wait_group %0;" :: "n"(N) : "memory");
}
// ---- mbarrier ----
static __device__ __forceinline__ void mb_init(uint32_t a, uint32_t cnt) {
    asm volatile("mbarrier.init.shared.b64 [%0], %1;" :: "r"(a), "r"(cnt) : "memory");
}
static __device__ __forceinline__ void mb_arrive(uint32_t a) {
    asm volatile("{ .reg .b64 t; mbarrier.arrive.shared.b64 t, [%0]; }" :: "r"(a) : "memory");
}
// NOINC is load-bearing: default form pre-increments pending count -> deadlock (R9/R10).
static __device__ __forceinline__ void cp_mb_arrive_noinc(uint32_t a) {
    asm volatile("cp.async.mbarrier.arrive.noinc.shared.b64 [%0];" :: "r"(a) : "memory");
}
static __device__ __forceinline__ void mb_wait(uint32_t a, uint32_t parity) {
    asm volatile(
        "{\n\t.reg .pred P1;\n\t"
        "W_%=:\n\t"
        "mbarrier.try_wait.parity.shared::cta.b64 P1, [%0], %1, 0x989680;\n\t"
        "@P1 bra D_%=;\n\t"
        "bra W_%=;\n\t"
        "D_%=:\n\t}"
        :: "r"(a), "r"(parity) : "memory");
}

// ---------------- merged preprocessing: cvt_x + 3x tr_head + tr_wo ----------------
__global__ __launch_bounds__(256) void prep(
    const float* __restrict__ x,
    const float* __restrict__ wq, const float* __restrict__ wk,
    const float* __restrict__ wv, const float* __restrict__ wo)
{
    const int b = blockIdx.x;
    if (b < 3072) {
        int i = b * 256 + threadIdx.x;
        float4 v = ((const float4*)x)[i];
        ((uint4*)g_xt)[i] = cvt4(v);
        return;
    }
    __shared__ float t[64][65];
    if (b < 3504) {
        const int bb = b - 3072;
        const int sel = bb / 144, r = bb % 144;
        const int k0 = (r % 12) * 64, h = r / 12;
        const float* src = (sel == 0) ? wq : (sel == 1) ? wk : wv;
        const float* s = src + (size_t)h * CC * DH;
        #pragma unroll
        for (int i = 0; i < 16; i++) {
            int e = threadIdx.x + i * 256; int kr = e >> 6, d = e & 63;
            t[kr][d] = s[(size_t)(k0 + kr) * DH + d];
        }
        __syncthreads();
        const int j0 = sel * CC;
        #pragma unroll
        for (int i = 0; i < 16; i++) {
            int e = threadIdx.x + i * 256; int d = e >> 6, kr = e & 63;
            g_wt[(size_t)(j0 + h * DH + d) * CC + k0 + kr] = __uint_as_float(tf32r(t[kr][d]));
        }
    } else {
        const int r = b - 3504;
        const int c0 = (r % 12) * 64, n0 = (r / 12) * 64;
        #pragma unroll
        for (int i = 0; i < 16; i++) {
            int e = threadIdx.x + i * 256; int cr = e >> 6, n = e & 63;
            t[cr][n] = wo[(size_t)(c0 + cr) * CC + n0 + n];
        }
        __syncthreads();
        #pragma unroll
        for (int i = 0; i < 16; i++) {
            int e = threadIdx.x + i * 256; int n = e >> 6, cr = e & 63;
            g_wot[(size_t)(n0 + n) * CC + c0 + cr] = __uint_as_float(tf32r(t[cr][n]));
        }
    }
}

// ---------------- GEMM qkv (tf32 mma.sync, 3-stage cp.async, 128x128 tile) ----------
#define GBUF 4608              // 128*36 u32 per matrix
#define GBUFSZ 9216            // per stage (A+B)

__global__ __launch_bounds__(256, 2) void gemm_qkv(
    const float* __restrict__ Am, const float* __restrict__ Bm,
    const float* __restrict__ bq, const float* __restrict__ bk,
    const float* __restrict__ bv)
{
    extern __shared__ uint32_t sm[];
    const uint32_t usm = smem_u32(sm);
    const int tid = threadIdx.x;
    const int warp = tid >> 5, lane = tid & 31;
    const int g = lane >> 2, q = lane & 3;
    const int warp_m = warp & 3, warp_n = warp >> 2;
    const int m0 = blockIdx.x * 128, n0 = blockIdx.y * 128;

    auto ldgsts = [&](int k0, int buf) {
        const uint32_t uA = usm + buf * GBUFSZ * 4;
        const uint32_t uB = uA + GBUF * 4;
        #pragma unroll
        for (int i = 0; i < 4; i++) {
            int idx = tid + i * 256; int r = idx >> 3, cc = idx & 7;
            cpa(uA + (r * 36 + cc * 4) * 4, Am + (size_t)(m0 + r) * CC + k0 + cc * 4);
            cpa(uB + (r * 36 + cc * 4) * 4, Bm + (size_t)(n0 + r) * CC + k0 + cc * 4);
        }
        cp_commit();
    };

    float Cf[2][8][4];
    #pragma unroll
    for (int tm = 0; tm < 2; tm++)
        #pragma unroll
        for (int tn = 0; tn < 8; tn++)
            #pragma unroll
            for (int k = 0; k < 4; k++) Cf[tm][tn][k] = 0.f;

    ldgsts(0, 0);
    ldgsts(32, 1);

    int buf = 0;
    for (int c = 0; c < 24; c++) {
        cp_wait<1>();
        __syncthreads();
        if (c < 22) ldgsts((c + 2) * 32, (c + 2) % 3);
        const uint32_t* sA = sm + buf * GBUFSZ;
        const uint32_t* sB = sA + GBUF;
        #pragma unroll
        for (int ks = 0; ks < 4; ks++) {
            uint32_t a[2][4];
            #pragma unroll
            for (int tm = 0; tm < 2; tm++) {
                int row = warp_m * 32 + tm * 16 + g;
                a[tm][0] = sA[row * 36 + ks * 8 + q];
                a[tm][1] = sA[(row + 8) * 36 + ks * 8 + q];
                a[tm][2] = sA[row * 36 + ks * 8 + q + 4];
                a[tm][3] = sA[(row + 8) * 36 + ks * 8 + q + 4];
            }
            #pragma unroll
            for (int tn = 0; tn < 8; tn++) {
                uint32_t b[2];
                int col = warp_n * 64 + tn * 8 + g;
                b[0] = sB[col * 36 + ks * 8 + q];
                b[1] = sB[col * 36 + ks * 8 + q + 4];
                mma8(Cf[0][tn], a[0], b);
                mma8(Cf[1][tn], a[1], b);
            }
        }
        buf = (buf + 1) % 3;
    }

    const int jb = n0 + warp_n * 64;
    const float c1 = 0.18033688011112042f;   // 0.125 * log2(e)
    const int sel = jb / CC, rem = jb % CC, h = rem >> 6;
    const float* bias = (sel == 0) ? bq : (sel == 1) ? bk : bv;
    // V key-permutation: row t -> (t & ~7) | ((t&1)*4 + ((t&7)>>1)); low 3 bits of
    // this thread's rows are exactly g.
    const int gp = (g & 1) * 4 + (g >> 1);
    #pragma unroll
    for (int tm = 0; tm < 2; tm++) {
        const int t0 = m0 + warp_m * 32 + tm * 16 + g;
        const int t0p = (t0 - g) + gp;     // permuted row for V
        #pragma unroll
        for (int tn = 0; tn < 8; tn++) {
            const int d = tn * 8 + 2 * q;
            const float b0 = bias[h * DH + d], b1 = bias[h * DH + d + 1];
            float v00 = Cf[tm][tn][0] + b0, v01 = Cf[tm][tn][1] + b1;
            float v10 = Cf[tm][tn][2] + b0, v11 = Cf[tm][tn][3] + b1;
            if (sel == 0) {
                float* dst = g_q + (size_t)h * TT * DH;
                uint2 p0 = { tf32r(v00 * c1), tf32r(v01 * c1) };
                uint2 p1 = { tf32r(v10 * c1), tf32r(v11 * c1) };
                *(uint2*)(dst + (size_t)t0 * DH + d) = p0;
                *(uint2*)(dst + (size_t)(t0 + 8) * DH + d) = p1;
            } else if (sel == 1) {
                float* dst = g_k + (size_t)h * TT * DH;
                uint2 p0 = { tf32r(v00), tf32r(v01) };
                uint2 p1 = { tf32r(v10), tf32r(v11) };
                *(uint2*)(dst + (size_t)t0 * DH + d) = p0;
                *(uint2*)(dst + (size_t)(t0 + 8) * DH + d) = p1;
            } else {
                float* dst = g_vt + (size_t)h * DH * TT;
                dst[(size_t)d * TT + t0p]           = __uint_as_float(tf32r(v00));
                dst[(size_t)(d + 1) * TT + t0p]     = __uint_as_float(tf32r(v01));
                dst[(size_t)d * TT + t0p + 8]       = __uint_as_float(tf32r(v10));
                dst[(size_t)(d + 1) * TT + t0p + 8] = __uint_as_float(tf32r(v11));
            }
        }
    }
}

// ---------------- GEMM out (128x64 tile, 128 threads, 384 CTAs for balance) ----------
// 4 warps of 32x64 (same per-warp shape/ratio as gemm_qkv). Same k-chunk order ->
// bit-identical per-element arithmetic vs the 128x128 version.
#define OBUFA 4608             // 128*36 u32
#define OBUFB 2304             // 64*36 u32
#define OBUFSZ 6912            // per stage

__global__ __launch_bounds__(128, 2) void gemm_out(
    const float* __restrict__ Am, const float* __restrict__ Bm,
    const float* __restrict__ bo, float* __restrict__ outp)
{
    extern __shared__ uint32_t sm[];
    const uint32_t usm = smem_u32(sm);
    const int tid = threadIdx.x;
    const int warp = tid >> 5, lane = tid & 31;
    const int g = lane >> 2, q = lane & 3;
    const int m0 = blockIdx.x * 128, n0 = blockIdx.y * 64;

    auto ldgsts = [&](int k0, int buf) {
        const uint32_t uA = usm + buf * OBUFSZ * 4;
        const uint32_t uB = uA + OBUFA * 4;
        #pragma unroll
        for (int i = 0; i < 8; i++) {
            int idx = tid + i * 128; int r = idx >> 3, cc = idx & 7;
            cpa(uA + (r * 36 + cc * 4) * 4, Am + (size_t)(m0 + r) * CC + k0 + cc * 4);
        }
        #pragma unroll
        for (int i = 0; i < 4; i++) {
            int idx = tid + i * 128; int r = idx >> 3, cc = idx & 7;
            cpa(uB + (r * 36 + cc * 4) * 4, Bm + (size_t)(n0 + r) * CC + k0 + cc * 4);
        }
        cp_commit();
    };

    float Cf[2][8][4];
    #pragma unroll
    for (int tm = 0; tm < 2; tm++)
        #pragma unroll
        for (int tn = 0; tn < 8; tn++)
            #pragma unroll
            for (int k = 0; k < 4; k++) Cf[tm][tn][k] = 0.f;

    ldgsts(0, 0);
    ldgsts(32, 1);

    int buf = 0;
    for (int c = 0; c < 24; c++) {
        cp_wait<1>();
        __syncthreads();
        if (c < 22) ldgsts((c + 2) * 32, (c + 2) % 3);
        const uint32_t* sA = sm + buf * OBUFSZ;
        const uint32_t* sB = sA + OBUFA;
        #pragma unroll
        for (int ks = 0; ks < 4; ks++) {
            uint32_t a[2][4];
            #pragma unroll
            for (int tm = 0; tm < 2; tm++) {
                int row = warp * 32 + tm * 16 + g;
                a[tm][0] = sA[row * 36 + ks * 8 + q];
                a[tm][1] = sA[(row + 8) * 36 + ks * 8 + q];
                a[tm][2] = sA[row * 36 + ks * 8 + q + 4];
                a[tm][3] = sA[(row + 8) * 36 + ks * 8 + q + 4];
            }
            #pragma unroll
            for (int tn = 0; tn < 8; tn++) {
                uint32_t b[2];
                int col = tn * 8 + g;
                b[0] = sB[col * 36 + ks * 8 + q];
                b[1] = sB[col * 36 + ks * 8 + q + 4];
                mma8(Cf[0][tn], a[0], b);
                mma8(Cf[1][tn], a[1], b);
            }
        }
        buf = (buf + 1) % 3;
    }

    #pragma unroll
    for (int tm = 0; tm < 2; tm++) {
        const int t0 = m0 + warp * 32 + tm * 16 + g;
        #pragma unroll
        for (int tn = 0; tn < 8; tn++) {
            const int j = n0 + tn * 8 + 2 * q;
            const float b0 = bo[j], b1 = bo[j + 1];
            float2 v0 = { Cf[tm][tn][0] + b0, Cf[tm][tn][1] + b1 };
            float2 v1 = { Cf[tm][tn][2] + b0, Cf[tm][tn][3] + b1 };
            *(float2*)(outp + (size_t)t0 * CC + j) = v0;
            *(float2*)(outp + (size_t)(t0 + 8) * CC + j) = v1;
        }
    }
}

// ---------------- flash attention (fine split-K + register-direct P feed) ------------
// grid.x = 80 per head (descending work), parts of <=16 key-blocks (see R13).
// PV's A-fragment is built from S's C-fragment registers (a = {c0,c2,c1,c3});
// V's key-slots are pre-permuted in g_vt so the k-interpretation matches.
#define ABUF 4352   // 64*68

__global__ __launch_bounds__(128, 2) void attn()
{
    extern __shared__ uint32_t sm[];
    __shared__ __align__(8) unsigned long long mbar_s[4];  // full0, full1, empty0, empty1
    uint32_t* Ps = sm;                 // Q staging only
    const uint32_t uPs = smem_u32(sm);
    const uint32_t ubar = smem_u32(mbar_s);

    const int tid = threadIdx.x;
    const int warp = tid >> 5, lane = tid & 31;
    const int g = lane >> 2, q = lane & 3;
    const int h = blockIdx.y;
    const int rb = warp * 32;

    const int bx = blockIdx.x;
    int qb, part, np;
    if (bx < 32)      { qb = 31 - (bx >> 2);        part = bx & 3;        np = 4; }
    else if (bx < 56) { int t = bx - 32; qb = 23 - t / 3; part = t % 3;   np = 3; }
    else if (bx < 72) { int t = bx - 56; qb = 15 - (t >> 1); part = t & 1; np = 2; }
    else              { qb = 7 - (bx - 72);          part = 0;            np = 1; }
    const int W  = 2 * qb + 2;
    const int j0 = (W * part) / np;
    const int j1 = (W * (part + 1)) / np;
    const int nloc = j1 - j0;
    const bool split = (np > 1);

    const float* Qg = g_q  + (size_t)h * TT * DH + (size_t)qb * 128 * DH;
    const float* Kg = g_k  + (size_t)h * TT * DH;
    const float* Vg = g_vt + (size_t)h * DH * TT;

    if (tid == 0) {
        mb_init(ubar + 0, 128);   // full0
        mb_init(ubar + 8, 128);   // full1
        mb_init(ubar + 16, 4);    // empty0
        mb_init(ubar + 24, 4);    // empty1
    }

    auto load_kv = [&](int j, int buf) {
        const uint32_t uK = uPs + (8704 + buf * ABUF) * 4;
        const uint32_t uV = uPs + (17408 + buf * ABUF) * 4;
        #pragma unroll
        for (int i = 0; i < 8; i++) {
            int idx = tid + i * 128; int r = idx >> 4, cc = idx & 15;
            cpa(uK + (r * 68 + cc * 4) * 4, Kg + (size_t)(j * 64 + r) * DH + cc * 4);
            cpa(uV + (r * 68 + cc * 4) * 4, Vg + (size_t)r * TT + j * 64 + cc * 4);
        }
    };

    // prologue: stage Q into Ps, load first KV block (group wait + CTA barrier,
    // which also publishes the mbarrier inits)
    #pragma unroll
    for (int i = 0; i < 16; i++) {
        int idx = tid + i * 128; int r = idx >> 4, cc = idx & 15;
        cpa(uPs + (r * 68 + cc * 4) * 4, Qg + (size_t)r * DH + cc * 4);
    }
    load_kv(j0, 0);
    cp_commit();
    cp_wait<0>();
    __syncthreads();

    // Q fragments -> registers (warp-private rows)
    uint32_t A[2][8][4];
    #pragma unroll
    for (int tm = 0; tm < 2; tm++) {
        const int base = rb + tm * 16;
        #pragma unroll
        for (int ks = 0; ks < 8; ks++) {
            A[tm][ks][0] = Ps[(base + g) * 68 + ks * 8 + q];
            A[tm][ks][1] = Ps[(base + 8 + g) * 68 + ks * 8 + q];
            A[tm][ks][2] = Ps[(base + g) * 68 + ks * 8 + q + 4];
            A[tm][ks][3] = Ps[(base + 8 + g) * 68 + ks * 8 + q + 4];
        }
    }

    float O[2][8][4];
    #pragma unroll
    for (int tm = 0; tm < 2; tm++)
        #pragma unroll
        for (int tn = 0; tn < 8; tn++)
            #pragma unroll
            for (int k = 0; k < 4; k++) O[tm][tn][k] = 0.f;
    float mv[4], lv[4];
    #pragma unroll
    for (int i = 0; i < 4; i++) { mv[i] = -1e30f; lv[i] = 0.f; }

    const int r0 = qb * 128 + rb + g;

    // per-warp parities: full start 0; empty0 starts 0, empty1 starts 1
    int pf0 = 0, pf1 = 0, pe0 = 0, pe1 = 1;

    for (int jj = 0; jj < nloc; jj++) {
        const int j = j0 + jj;
        const int b = jj & 1;
        if (jj) {
            if (b == 0) { mb_wait(ubar + 0, pf0); pf0 ^= 1; }
            else        { mb_wait(ubar + 8, pf1); pf1 ^= 1; }
        }
        if (jj + 1 < nloc) {
            const int nb = (jj + 1) & 1;
            if (nb == 0) { mb_wait(ubar + 16, pe0); pe0 ^= 1; }
            else         { mb_wait(ubar + 24, pe1); pe1 ^= 1; }
            load_kv(j + 1, nb);
            cp_mb_arrive_noinc(ubar + nb * 8);   // arm full[nb] (all 128 threads)
        }
        const uint32_t* Ks = sm + 8704 + b * ABUF;
        const uint32_t* Vs = sm + 17408 + b * ABUF;

        // S = Q @ K^T (log2 domain; Q pre-scaled)
        float S[2][8][4];
        #pragma unroll
        for (int tm = 0; tm < 2; tm++)
            #pragma unroll
            for (int tn = 0; tn < 8; tn++)
                #pragma unroll
                for (int k = 0; k < 4; k++) S[tm][tn][k] = 0.f;
        #pragma unroll
        for (int ks = 0; ks < 8; ks++) {
            #pragma unroll
            for (int tn = 0; tn < 8; tn++) {
                uint32_t bb[2];
                bb[0] = Ks[(tn * 8 + g) * 68 + ks * 8 + q];
                bb[1] = Ks[(tn * 8 + g) * 68 + ks * 8 + q + 4];
                mma8(S[0][tn], A[0][ks], bb);
                mma8(S[1][tn], A[1][ks], bb);
            }
        }

        // causal mask (diagonal key-blocks only; j is absolute; cols = logical keys)
        if (j >= 2 * qb) {
            const int kb = j * 64;
            #pragma unroll
            for (int tn = 0; tn < 8; tn++) {
                const int col = kb + tn * 8 + 2 * q;
                #pragma unroll
                for (int tm = 0; tm < 2; tm++) {
                    const int ra = r0 + tm * 16, rb2 = ra + 8;
                    if (col > ra)      S[tm][tn][0] = -1e30f;
                    if (col + 1 > ra)  S[tm][tn][1] = -1e30f;
                    if (col > rb2)     S[tm][tn][2] = -1e30f;
                    if (col + 1 > rb2) S[tm][tn][3] = -1e30f;
                }
            }
        }

        // online softmax over 4 rows
        float tmax[4] = { -1e30f, -1e30f, -1e30f, -1e30f };
        #pragma unroll
        for (int tm = 0; tm < 2; tm++)
            #pragma unroll
            for (int tn = 0; tn < 8; tn++) {
                tmax[tm * 2]     = fmaxf(tmax[tm * 2],     fmaxf(S[tm][tn][0], S[tm][tn][1]));
                tmax[tm * 2 + 1] = fmaxf(tmax[tm * 2 + 1], fmaxf(S[tm][tn][2], S[tm][tn][3]));
            }
        float al[4];
        #pragma unroll
        for (int i = 0; i < 4; i++) {
            tmax[i] = fmaxf(tmax[i], __shfl_xor_sync(0xffffffffu, tmax[i], 1));
            tmax[i] = fmaxf(tmax[i], __shfl_xor_sync(0xffffffffu, tmax[i], 2));
            const float mn = fmaxf(mv[i], tmax[i]);
            al[i] = ex2(mv[i] - mn);
            mv[i] = mn;
        }
        float rs[4] = { 0.f, 0.f, 0.f, 0.f };
        #pragma unroll
        for (int tm = 0; tm < 2; tm++)
            #pragma unroll
            for (int tn = 0; tn < 8; tn++) {
                S[tm][tn][0] = ex2(S[tm][tn][0] - mv[tm * 2]);
                S[tm][tn][1] = ex2(S[tm][tn][1] - mv[tm * 2]);
                S[tm][tn][2] = ex2(S[tm][tn][2] - mv[tm * 2 + 1]);
                S[tm][tn][3] = ex2(S[tm][tn][3] - mv[tm * 2 + 1]);
                rs[tm * 2]     += S[tm][tn][0] + S[tm][tn][1];
                rs[tm * 2 + 1] += S[tm][tn][2] + S[tm][tn][3];
            }
        #pragma unroll
        for (int i = 0; i < 4; i++) {
            rs[i] += __shfl_xor_sync(0xffffffffu, rs[i], 1);
            rs[i] += __shfl_xor_sync(0xffffffffu, rs[i], 2);
            lv[i] = lv[i] * al[i] + rs[i];
        }

        // rescale O, accumulate P @ V directly from S registers
        // (A-fragment = {c0, c2, c1, c3}; V key-slots pre-permuted to match)
        #pragma unroll
        for (int tm = 0; tm < 2; tm++)
            #pragma unroll
            for (int tn = 0; tn < 8; tn++) {
                O[tm][tn][0] *= al[tm * 2];     O[tm][tn][1] *= al[tm * 2];
                O[tm][tn][2] *= al[tm * 2 + 1]; O[tm][tn][3] *= al[tm * 2 + 1];
            }
        #pragma unroll
        for (int ks = 0; ks < 8; ks++) {
            uint32_t a[2][4];
            #pragma unroll
            for (int tm = 0; tm < 2; tm++) {
                a[tm][0] = tf32r(S[tm][ks][0]);
                a[tm][1] = tf32r(S[tm][ks][2]);
                a[tm][2] = tf32r(S[tm][ks][1]);
                a[tm][3] = tf32r(S[tm][ks][3]);
            }
            #pragma unroll
            for (int tn = 0; tn < 8; tn++) {
                uint32_t bb[2];
                bb[0] = Vs[(tn * 8 + g) * 68 + ks * 8 + q];
                bb[1] = Vs[(tn * 8 + g) * 68 + ks * 8 + q + 4];
                mma8(O[0][tn], a[0], bb);
                mma8(O[1][tn], a[1], bb);
            }
        }
        if (lane == 0) mb_arrive(ubar + 16 + b * 8);   // release stage b
    }

    if (!split) {
        // unsplit: normalize and write g_att (tf32-rounded for the out GEMM)
        #pragma unroll
        for (int tm = 0; tm < 2; tm++) {
            const int ra = r0 + tm * 16;
            const float i0 = 1.f / lv[tm * 2], i1 = 1.f / lv[tm * 2 + 1];
            #pragma unroll
            for (int tn = 0; tn < 8; tn++) {
                const int d = tn * 8 + 2 * q;
                uint2 v0 = { tf32r(O[tm][tn][0] * i0), tf32r(O[tm][tn][1] * i0) };
                uint2 v1 = { tf32r(O[tm][tn][2] * i1), tf32r(O[tm][tn][3] * i1) };
                *(uint2*)(g_att + (size_t)ra * CC + h * DH + d) = v0;
                *(uint2*)(g_att + (size_t)(ra + 8) * CC + h * DH + d) = v1;
            }
        }
    } else {
        // split: write unnormalized O + (m, l) to scratch (rows 0..3071 per head)
        const int sb = (qb - 8) * 128;
        float* poB = g_po + ((size_t)part * HH + h) * 3072 * 64;
        #pragma unroll
        for (int tm = 0; tm < 2; tm++) {
            const int lr = rb + tm * 16 + g;
            #pragma unroll
            for (int tn = 0; tn < 8; tn++) {
                const int d = tn * 8 + 2 * q;
                float2 v0 = { O[tm][tn][0], O[tm][tn][1] };
                float2 v1 = { O[tm][tn][2], O[tm][tn][3] };
                *(float2*)(poB + (size_t)(sb + lr) * 64 + d) = v0;
                *(float2*)(poB + (size_t)(sb + lr + 8) * 64 + d) = v1;
            }
            if (q == 0) {
                const size_t mi = ((size_t)part * HH + h) * 3072 + sb;
                g_pm[mi + lr]     = mv[tm * 2];     g_pl[mi + lr]     = lv[tm * 2];
                g_pm[mi + lr + 8] = mv[tm * 2 + 1]; g_pl[mi + lr + 8] = lv[tm * 2 + 1];
            }
        }
    }
}

// ---------------- merge split-K partials (token rows 1024..4095, 2-4 parts) ----------
__global__ __launch_bounds__(256) void merge_k()
{
    const int idx = blockIdx.x * 256 + threadIdx.x;   // 12 * 3072 * 16 = 589824
    const int d4  = (idx & 15) * 4;
    const int row = (idx >> 4) % 3072;
    const int h   = idx / (3072 * 16);

    const int qb = 8 + (row >> 7);
    const int np = (qb >= 24) ? 4 : (qb >= 16) ? 3 : 2;

    const size_t mi0 = (size_t)h * 3072 + row;
    float m = -1e30f;
    #pragma unroll
    for (int p = 0; p < 4; p++)
        if (p < np) m = fmaxf(m, g_pm[(size_t)p * HH * 3072 + mi0]);

    float den = 0.f;
    float4 acc = { 0.f, 0.f, 0.f, 0.f };
    #pragma unroll
    for (int p = 0; p < 4; p++) {
        if (p >= np) break;
        const size_t mi = (size_t)p * HH * 3072 + mi0;
        const float w = ex2(g_pm[mi] - m);
        den += g_pl[mi] * w;
        const float4 o = *(const float4*)(g_po + ((size_t)p * HH + h) * 3072 * 64
                                               + (size_t)row * 64 + d4);
        acc.x += o.x * w; acc.y += o.y * w; acc.z += o.z * w; acc.w += o.w * w;
    }
    const float inv = 1.f / den;
    uint4 r;
    r.x = tf32r(acc.x * inv); r.y = tf32r(acc.y * inv);
    r.z = tf32r(acc.z * inv); r.w = tf32r(acc.w * inv);

    const int tok = qb * 128 + (row & 127);
    *(uint4*)(g_att + (size_t)tok * CC + h * DH + d4) = r;
}

// ---------------- launcher ----------------
extern "C" void kernel_launch(void* const* d_in, const int* in_sizes, int n_in,
                              void* d_out, int out_size)
{
    const float* x  = (const float*)d_in[0];
    const float* wq = (const float*)d_in[1];
    const float* bq = (const float*)d_in[2];
    const float* wk = (const float*)d_in[3];
    const float* bk = (const float*)d_in[4];
    const float* wv = (const float*)d_in[5];
    const float* bv = (const float*)d_in[6];
    const float* wo = (const float*)d_in[7];
    const float* bo = (const float*)d_in[8];

    const int GSM  = 3 * GBUFSZ * 4;    // 110592 B (qkv, 3-stage 128x128)
    const int OSM  = 3 * OBUFSZ * 4;    // 82944 B  (out, 3-stage 128x64)
    const int ASM  = 26112 * 4;         // 104448 B
    cudaFuncSetAttribute(gemm_qkv, cudaFuncAttributeMaxDynamicSharedMemorySize, GSM);
    cudaFuncSetAttribute(gemm_out, cudaFuncAttributeMaxDynamicSharedMemorySize, OSM);
    cudaFuncSetAttribute(attn,     cudaFuncAttributeMaxDynamicSharedMemorySize, ASM);

    float* xt_dev;  cudaGetSymbolAddress((void**)&xt_dev,  g_xt);
    float* wt_dev;  cudaGetSymbolAddress((void**)&wt_dev,  g_wt);
    float* wot_dev; cudaGetSymbolAddress((void**)&wot_dev, g_wot);
    float* att_dev; cudaGetSymbolAddress((void**)&att_dev, g_att);

    prep<<<3648, 256>>>(x, wq, wk, wv, wo);
    gemm_qkv<<<dim3(32, 18), 256, GSM>>>(xt_dev, wt_dev, bq, bk, bv);
    attn<<<dim3(80, 12), 128, ASM>>>();
    merge_k<<<2304, 256>>>();
    gemm_out<<<dim3(32, 12), 128, OSM>>>(att_dev, wot_dev, bo, (float*)d_out);
}

// round 17
// speedup vs baseline: 1.1727x; 1.0239x over previous
#include <cuda_runtime.h>
#include <cstdint>

#define TT 4096
#define CC 768
#define HH 12
#define DH 64

// ---------------- device scratch (allocation-free rule) ----------------
__device__ float g_xt [TT * CC];        // x, tf32-rounded
__device__ float g_q  [HH * TT * DH];   // [h][t][d], pre-scaled by 0.125*log2e, tf32
__device__ float g_k  [HH * TT * DH];   // [h][t][d], tf32
// V transposed [h][d][t], tf32, with t PERMUTED within 8-groups:
// slot p holds logical key 2p (p<4) / 2(p-4)+1 (p>=4)  <=>  key k stored at
// (k&~7) | ((k&1)*4 + ((k&7)>>1)). This makes S's C-fragment directly usable as
// the PV A-fragment (a = {c0,c2,c1,c3}) -- no P smem round-trip.
__device__ float g_vt [HH * DH * TT];
__device__ float g_att[TT * CC];        // concat heads, tf32
__device__ float g_wt [3 * CC * CC];    // qkv weights [j][k], tf32
__device__ float g_wot[CC * CC];        // wo as [n][k], tf32
// split-K attention partials (qb 8..31 -> scratch rows 0..3071 per head, up to 4 parts)
__device__ float g_po[4 * HH * 3072 * DH];   // unnormalized O per part
__device__ float g_pm[4 * HH * 3072];        // row max (log2 domain)
__device__ float g_pl[4 * HH * 3072];        // row sum

// ---------------- helpers ----------------
static __device__ __forceinline__ uint32_t smem_u32(const void* p) {
    uint32_t a;
    asm("{ .reg .u64 t; cvta.to.shared.u64 t, %1; cvt.u32.u64 %0, t; }" : "=r"(a) : "l"(p));
    return a;
}
static __device__ __forceinline__ uint32_t tf32r(float f) {
    uint32_t u; asm("cvt.rna.tf32.f32 %0, %1;" : "=r"(u) : "f"(f)); return u;
}
static __device__ __forceinline__ float ex2(float x) {
    float y; asm("ex2.approx.f32 %0, %1;" : "=f"(y) : "f"(x)); return y;
}
static __device__ __forceinline__ void mma8(float* d, const uint32_t* a, const uint32_t* b) {
    asm volatile(
        "mma.sync.aligned.m16n8k8.row.col.f32.tf32.tf32.f32 "
        "{%0,%1,%2,%3}, {%4,%5,%6,%7}, {%8,%9}, {%0,%1,%2,%3};"
        : "+f"(d[0]), "+f"(d[1]), "+f"(d[2]), "+f"(d[3])
        : "r"(a[0]), "r"(a[1]), "r"(a[2]), "r"(a[3]), "r"(b[0]), "r"(b[1]));
}
static __device__ __forceinline__ uint4 cvt4(float4 v) {
    uint4 t; t.x = tf32r(v.x); t.y = tf32r(v.y); t.z = tf32r(v.z); t.w = tf32r(v.w);
    return t;
}
static __device__ __forceinline__ void cpa(uint32_t dst, const void* src) {
    asm volatile("cp.async.cg.shared.global [%0], [%1], 16;" :: "r"(dst), "l"(src));
}
static __device__ __forceinline__ void cp_commit() {
    asm volatile("cp.async.commit_group;" ::: "memory");
}
template <int N> static __device__ __forceinline__ void cp_wait() {
    asm volatile("cp.async.wait_group %0;" :: "n"(N) : "memory");
}
// ---- mbarrier ----
static __device__ __forceinline__ void mb_init(uint32_t a, uint32_t cnt) {
    asm volatile("mbarrier.init.shared.b64 [%0], %1;" :: "r"(a), "r"(cnt) : "memory");
}
static __device__ __forceinline__ void mb_arrive(uint32_t a) {
    asm volatile("{ .reg .b64 t; mbarrier.arrive.shared.b64 t, [%0]; }" :: "r"(a) : "memory");
}
// NOINC is load-bearing: default form pre-increments pending count -> deadlock (R9/R10).
static __device__ __forceinline__ void cp_mb_arrive_noinc(uint32_t a) {
    asm volatile("cp.async.mbarrier.arrive.noinc.shared.b64 [%0];" :: "r"(a) : "memory");
}
static __device__ __forceinline__ void mb_wait(uint32_t a, uint32_t parity) {
    asm volatile(
        "{\n\t.reg .pred P1;\n\t"
        "W_%=:\n\t"
        "mbarrier.try_wait.parity.shared::cta.b64 P1, [%0], %1, 0x989680;\n\t"
        "@P1 bra D_%=;\n\t"
        "bra W_%=;\n\t"
        "D_%=:\n\t}"
        :: "r"(a), "r"(parity) : "memory");
}

// ---------------- merged preprocessing: cvt_x + 3x tr_head + tr_wo ----------------
__global__ __launch_bounds__(256) void prep(
    const float* __restrict__ x,
    const float* __restrict__ wq, const float* __restrict__ wk,
    const float* __restrict__ wv, const float* __restrict__ wo)
{
    const int b = blockIdx.x;
    if (b < 3072) {
        int i = b * 256 + threadIdx.x;
        float4 v = ((const float4*)x)[i];
        ((uint4*)g_xt)[i] = cvt4(v);
        return;
    }
    __shared__ float t[64][65];
    if (b < 3504) {
        const int bb = b - 3072;
        const int sel = bb / 144, r = bb % 144;
        const int k0 = (r % 12) * 64, h = r / 12;
        const float* src = (sel == 0) ? wq : (sel == 1) ? wk : wv;
        const float* s = src + (size_t)h * CC * DH;
        #pragma unroll
        for (int i = 0; i < 16; i++) {
            int e = threadIdx.x + i * 256; int kr = e >> 6, d = e & 63;
            t[kr][d] = s[(size_t)(k0 + kr) * DH + d];
        }
        __syncthreads();
        const int j0 = sel * CC;
        #pragma unroll
        for (int i = 0; i < 16; i++) {
            int e = threadIdx.x + i * 256; int d = e >> 6, kr = e & 63;
            g_wt[(size_t)(j0 + h * DH + d) * CC + k0 + kr] = __uint_as_float(tf32r(t[kr][d]));
        }
    } else {
        const int r = b - 3504;
        const int c0 = (r % 12) * 64, n0 = (r / 12) * 64;
        #pragma unroll
        for (int i = 0; i < 16; i++) {
            int e = threadIdx.x + i * 256; int cr = e >> 6, n = e & 63;
            t[cr][n] = wo[(size_t)(c0 + cr) * CC + n0 + n];
        }
        __syncthreads();
        #pragma unroll
        for (int i = 0; i < 16; i++) {
            int e = threadIdx.x + i * 256; int n = e >> 6, cr = e & 63;
            g_wot[(size_t)(n0 + n) * CC + c0 + cr] = __uint_as_float(tf32r(t[cr][n]));
        }
    }
}

// ---------------- GEMM qkv (tf32 mma.sync, 3-stage cp.async, 128x128 tile) ----------
#define GBUF 4608              // 128*36 u32 per matrix
#define GBUFSZ 9216            // per stage (A+B)

__global__ __launch_bounds__(256, 2) void gemm_qkv(
    const float* __restrict__ Am, const float* __restrict__ Bm,
    const float* __restrict__ bq, const float* __restrict__ bk,
    const float* __restrict__ bv)
{
    extern __shared__ uint32_t sm[];
    const uint32_t usm = smem_u32(sm);
    const int tid = threadIdx.x;
    const int warp = tid >> 5, lane = tid & 31;
    const int g = lane >> 2, q = lane & 3;
    const int warp_m = warp & 3, warp_n = warp >> 2;
    const int m0 = blockIdx.x * 128, n0 = blockIdx.y * 128;

    auto ldgsts = [&](int k0, int buf) {
        const uint32_t uA = usm + buf * GBUFSZ * 4;
        const uint32_t uB = uA + GBUF * 4;
        #pragma unroll
        for (int i = 0; i < 4; i++) {
            int idx = tid + i * 256; int r = idx >> 3, cc = idx & 7;
            cpa(uA + (r * 36 + cc * 4) * 4, Am + (size_t)(m0 + r) * CC + k0 + cc * 4);
            cpa(uB + (r * 36 + cc * 4) * 4, Bm + (size_t)(n0 + r) * CC + k0 + cc * 4);
        }
        cp_commit();
    };

    float Cf[2][8][4];
    #pragma unroll
    for (int tm = 0; tm < 2; tm++)
        #pragma unroll
        for (int tn = 0; tn < 8; tn++)
            #pragma unroll
            for (int k = 0; k < 4; k++) Cf[tm][tn][k] = 0.f;

    ldgsts(0, 0);
    ldgsts(32, 1);

    int buf = 0;
    for (int c = 0; c < 24; c++) {
        cp_wait<1>();
        __syncthreads();
        if (c < 22) ldgsts((c + 2) * 32, (c + 2) % 3);
        const uint32_t* sA = sm + buf * GBUFSZ;
        const uint32_t* sB = sA + GBUF;
        #pragma unroll
        for (int ks = 0; ks < 4; ks++) {
            uint32_t a[2][4];
            #pragma unroll
            for (int tm = 0; tm < 2; tm++) {
                int row = warp_m * 32 + tm * 16 + g;
                a[tm][0] = sA[row * 36 + ks * 8 + q];
                a[tm][1] = sA[(row + 8) * 36 + ks * 8 + q];
                a[tm][2] = sA[row * 36 + ks * 8 + q + 4];
                a[tm][3] = sA[(row + 8) * 36 + ks * 8 + q + 4];
            }
            #pragma unroll
            for (int tn = 0; tn < 8; tn++) {
                uint32_t b[2];
                int col = warp_n * 64 + tn * 8 + g;
                b[0] = sB[col * 36 + ks * 8 + q];
                b[1] = sB[col * 36 + ks * 8 + q + 4];
                mma8(Cf[0][tn], a[0], b);
                mma8(Cf[1][tn], a[1], b);
            }
        }
        buf = (buf + 1) % 3;
    }

    const int jb = n0 + warp_n * 64;
    const float c1 = 0.18033688011112042f;   // 0.125 * log2(e)
    const int sel = jb / CC, rem = jb % CC, h = rem >> 6;
    const float* bias = (sel == 0) ? bq : (sel == 1) ? bk : bv;
    // V key-permutation: row t -> (t & ~7) | ((t&1)*4 + ((t&7)>>1)); low 3 bits of
    // this thread's rows are exactly g.
    const int gp = (g & 1) * 4 + (g >> 1);
    #pragma unroll
    for (int tm = 0; tm < 2; tm++) {
        const int t0 = m0 + warp_m * 32 + tm * 16 + g;
        const int t0p = (t0 - g) + gp;     // permuted row for V
        #pragma unroll
        for (int tn = 0; tn < 8; tn++) {
            const int d = tn * 8 + 2 * q;
            const float b0 = bias[h * DH + d], b1 = bias[h * DH + d + 1];
            float v00 = Cf[tm][tn][0] + b0, v01 = Cf[tm][tn][1] + b1;
            float v10 = Cf[tm][tn][2] + b0, v11 = Cf[tm][tn][3] + b1;
            if (sel == 0) {
                float* dst = g_q + (size_t)h * TT * DH;
                uint2 p0 = { tf32r(v00 * c1), tf32r(v01 * c1) };
                uint2 p1 = { tf32r(v10 * c1), tf32r(v11 * c1) };
                *(uint2*)(dst + (size_t)t0 * DH + d) = p0;
                *(uint2*)(dst + (size_t)(t0 + 8) * DH + d) = p1;
            } else if (sel == 1) {
                float* dst = g_k + (size_t)h * TT * DH;
                uint2 p0 = { tf32r(v00), tf32r(v01) };
                uint2 p1 = { tf32r(v10), tf32r(v11) };
                *(uint2*)(dst + (size_t)t0 * DH + d) = p0;
                *(uint2*)(dst + (size_t)(t0 + 8) * DH + d) = p1;
            } else {
                float* dst = g_vt + (size_t)h * DH * TT;
                dst[(size_t)d * TT + t0p]           = __uint_as_float(tf32r(v00));
                dst[(size_t)(d + 1) * TT + t0p]     = __uint_as_float(tf32r(v01));
                dst[(size_t)d * TT + t0p + 8]       = __uint_as_float(tf32r(v10));
                dst[(size_t)(d + 1) * TT + t0p + 8] = __uint_as_float(tf32r(v11));
            }
        }
    }
}

// ---------------- GEMM out (128x64 tile, 128 threads, 384 CTAs for balance) ----------
#define OBUFA 4608             // 128*36 u32
#define OBUFB 2304             // 64*36 u32
#define OBUFSZ 6912            // per stage

__global__ __launch_bounds__(128, 2) void gemm_out(
    const float* __restrict__ Am, const float* __restrict__ Bm,
    const float* __restrict__ bo, float* __restrict__ outp)
{
    extern __shared__ uint32_t sm[];
    const uint32_t usm = smem_u32(sm);
    const int tid = threadIdx.x;
    const int warp = tid >> 5, lane = tid & 31;
    const int g = lane >> 2, q = lane & 3;
    const int m0 = blockIdx.x * 128, n0 = blockIdx.y * 64;

    auto ldgsts = [&](int k0, int buf) {
        const uint32_t uA = usm + buf * OBUFSZ * 4;
        const uint32_t uB = uA + OBUFA * 4;
        #pragma unroll
        for (int i = 0; i < 8; i++) {
            int idx = tid + i * 128; int r = idx >> 3, cc = idx & 7;
            cpa(uA + (r * 36 + cc * 4) * 4, Am + (size_t)(m0 + r) * CC + k0 + cc * 4);
        }
        #pragma unroll
        for (int i = 0; i < 4; i++) {
            int idx = tid + i * 128; int r = idx >> 3, cc = idx & 7;
            cpa(uB + (r * 36 + cc * 4) * 4, Bm + (size_t)(n0 + r) * CC + k0 + cc * 4);
        }
        cp_commit();
    };

    float Cf[2][8][4];
    #pragma unroll
    for (int tm = 0; tm < 2; tm++)
        #pragma unroll
        for (int tn = 0; tn < 8; tn++)
            #pragma unroll
            for (int k = 0; k < 4; k++) Cf[tm][tn][k] = 0.f;

    ldgsts(0, 0);
    ldgsts(32, 1);

    int buf = 0;
    for (int c = 0; c < 24; c++) {
        cp_wait<1>();
        __syncthreads();
        if (c < 22) ldgsts((c + 2) * 32, (c + 2) % 3);
        const uint32_t* sA = sm + buf * OBUFSZ;
        const uint32_t* sB = sA + OBUFA;
        #pragma unroll
        for (int ks = 0; ks < 4; ks++) {
            uint32_t a[2][4];
            #pragma unroll
            for (int tm = 0; tm < 2; tm++) {
                int row = warp * 32 + tm * 16 + g;
                a[tm][0] = sA[row * 36 + ks * 8 + q];
                a[tm][1] = sA[(row + 8) * 36 + ks * 8 + q];
                a[tm][2] = sA[row * 36 + ks * 8 + q + 4];
                a[tm][3] = sA[(row + 8) * 36 + ks * 8 + q + 4];
            }
            #pragma unroll
            for (int tn = 0; tn < 8; tn++) {
                uint32_t b[2];
                int col = tn * 8 + g;
                b[0] = sB[col * 36 + ks * 8 + q];
                b[1] = sB[col * 36 + ks * 8 + q + 4];
                mma8(Cf[0][tn], a[0], b);
                mma8(Cf[1][tn], a[1], b);
            }
        }
        buf = (buf + 1) % 3;
    }

    #pragma unroll
    for (int tm = 0; tm < 2; tm++) {
        const int t0 = m0 + warp * 32 + tm * 16 + g;
        #pragma unroll
        for (int tn = 0; tn < 8; tn++) {
            const int j = n0 + tn * 8 + 2 * q;
            const float b0 = bo[j], b1 = bo[j + 1];
            float2 v0 = { Cf[tm][tn][0] + b0, Cf[tm][tn][1] + b1 };
            float2 v1 = { Cf[tm][tn][2] + b0, Cf[tm][tn][3] + b1 };
            *(float2*)(outp + (size_t)t0 * CC + j) = v0;
            *(float2*)(outp + (size_t)(t0 + 8) * CC + j) = v1;
        }
    }
}

// ---------------- flash attention (fine split-K + register-direct P feed) ------------
// grid.x = 80 per head (descending work), parts of <=16 key-blocks (see R13).
// PV's A-fragment is S's C-fragment registers passed RAW (a = {c0,c2,c1,c3});
// tf32 mma reads only the upper 19 bits, so fp32 bits = truncated tf32 (RZ vs RNA).
// V's key-slots are pre-permuted in g_vt so the k-interpretation matches.
#define ABUF 4352   // 64*68

__global__ __launch_bounds__(128, 2) void attn()
{
    extern __shared__ uint32_t sm[];
    __shared__ __align__(8) unsigned long long mbar_s[4];  // full0, full1, empty0, empty1
    uint32_t* Ps = sm;                 // Q staging only
    const uint32_t uPs = smem_u32(sm);
    const uint32_t ubar = smem_u32(mbar_s);

    const int tid = threadIdx.x;
    const int warp = tid >> 5, lane = tid & 31;
    const int g = lane >> 2, q = lane & 3;
    const int h = blockIdx.y;
    const int rb = warp * 32;

    const int bx = blockIdx.x;
    int qb, part, np;
    if (bx < 32)      { qb = 31 - (bx >> 2);        part = bx & 3;        np = 4; }
    else if (bx < 56) { int t = bx - 32; qb = 23 - t / 3; part = t % 3;   np = 3; }
    else if (bx < 72) { int t = bx - 56; qb = 15 - (t >> 1); part = t & 1; np = 2; }
    else              { qb = 7 - (bx - 72);          part = 0;            np = 1; }
    const int W  = 2 * qb + 2;
    const int j0 = (W * part) / np;
    const int j1 = (W * (part + 1)) / np;
    const int nloc = j1 - j0;
    const bool split = (np > 1);

    const float* Qg = g_q  + (size_t)h * TT * DH + (size_t)qb * 128 * DH;
    const float* Kg = g_k  + (size_t)h * TT * DH;
    const float* Vg = g_vt + (size_t)h * DH * TT;

    if (tid == 0) {
        mb_init(ubar + 0, 128);   // full0
        mb_init(ubar + 8, 128);   // full1
        mb_init(ubar + 16, 4);    // empty0
        mb_init(ubar + 24, 4);    // empty1
    }

    auto load_kv = [&](int j, int buf) {
        const uint32_t uK = uPs + (8704 + buf * ABUF) * 4;
        const uint32_t uV = uPs + (17408 + buf * ABUF) * 4;
        #pragma unroll
        for (int i = 0; i < 8; i++) {
            int idx = tid + i * 128; int r = idx >> 4, cc = idx & 15;
            cpa(uK + (r * 68 + cc * 4) * 4, Kg + (size_t)(j * 64 + r) * DH + cc * 4);
            cpa(uV + (r * 68 + cc * 4) * 4, Vg + (size_t)r * TT + j * 64 + cc * 4);
        }
    };

    // prologue: stage Q into Ps, load first KV block (group wait + CTA barrier,
    // which also publishes the mbarrier inits)
    #pragma unroll
    for (int i = 0; i < 16; i++) {
        int idx = tid + i * 128; int r = idx >> 4, cc = idx & 15;
        cpa(uPs + (r * 68 + cc * 4) * 4, Qg + (size_t)r * DH + cc * 4);
    }
    load_kv(j0, 0);
    cp_commit();
    cp_wait<0>();
    __syncthreads();

    // Q fragments -> registers (warp-private rows)
    uint32_t A[2][8][4];
    #pragma unroll
    for (int tm = 0; tm < 2; tm++) {
        const int base = rb + tm * 16;
        #pragma unroll
        for (int ks = 0; ks < 8; ks++) {
            A[tm][ks][0] = Ps[(base + g) * 68 + ks * 8 + q];
            A[tm][ks][1] = Ps[(base + 8 + g) * 68 + ks * 8 + q];
            A[tm][ks][2] = Ps[(base + g) * 68 + ks * 8 + q + 4];
            A[tm][ks][3] = Ps[(base + 8 + g) * 68 + ks * 8 + q + 4];
        }
    }

    float O[2][8][4];
    #pragma unroll
    for (int tm = 0; tm < 2; tm++)
        #pragma unroll
        for (int tn = 0; tn < 8; tn++)
            #pragma unroll
            for (int k = 0; k < 4; k++) O[tm][tn][k] = 0.f;
    float mv[4], lv[4];
    #pragma unroll
    for (int i = 0; i < 4; i++) { mv[i] = -1e30f; lv[i] = 0.f; }

    const int r0 = qb * 128 + rb + g;

    // per-warp parities: full start 0; empty0 starts 0, empty1 starts 1
    int pf0 = 0, pf1 = 0, pe0 = 0, pe1 = 1;

    for (int jj = 0; jj < nloc; jj++) {
        const int j = j0 + jj;
        const int b = jj & 1;
        if (jj) {
            if (b == 0) { mb_wait(ubar + 0, pf0); pf0 ^= 1; }
            else        { mb_wait(ubar + 8, pf1); pf1 ^= 1; }
        }
        if (jj + 1 < nloc) {
            const int nb = (jj + 1) & 1;
            if (nb == 0) { mb_wait(ubar + 16, pe0); pe0 ^= 1; }
            else         { mb_wait(ubar + 24, pe1); pe1 ^= 1; }
            load_kv(j + 1, nb);
            cp_mb_arrive_noinc(ubar + nb * 8);   // arm full[nb] (all 128 threads)
        }
        const uint32_t* Ks = sm + 8704 + b * ABUF;
        const uint32_t* Vs = sm + 17408 + b * ABUF;

        // S = Q @ K^T (log2 domain; Q pre-scaled)
        float S[2][8][4];
        #pragma unroll
        for (int tm = 0; tm < 2; tm++)
            #pragma unroll
            for (int tn = 0; tn < 8; tn++)
                #pragma unroll
                for (int k = 0; k < 4; k++) S[tm][tn][k] = 0.f;
        #pragma unroll
        for (int ks = 0; ks < 8; ks++) {
            #pragma unroll
            for (int tn = 0; tn < 8; tn++) {
                uint32_t bb[2];
                bb[0] = Ks[(tn * 8 + g) * 68 + ks * 8 + q];
                bb[1] = Ks[(tn * 8 + g) * 68 + ks * 8 + q + 4];
                mma8(S[0][tn], A[0][ks], bb);
                mma8(S[1][tn], A[1][ks], bb);
            }
        }

        // causal mask (diagonal key-blocks only; j is absolute; cols = logical keys)
        if (j >= 2 * qb) {
            const int kb = j * 64;
            #pragma unroll
            for (int tn = 0; tn < 8; tn++) {
                const int col = kb + tn * 8 + 2 * q;
                #pragma unroll
                for (int tm = 0; tm < 2; tm++) {
                    const int ra = r0 + tm * 16, rb2 = ra + 8;
                    if (col > ra)      S[tm][tn][0] = -1e30f;
                    if (col + 1 > ra)  S[tm][tn][1] = -1e30f;
                    if (col > rb2)     S[tm][tn][2] = -1e30f;
                    if (col + 1 > rb2) S[tm][tn][3] = -1e30f;
                }
            }
        }

        // online softmax over 4 rows
        float tmax[4] = { -1e30f, -1e30f, -1e30f, -1e30f };
        #pragma unroll
        for (int tm = 0; tm < 2; tm++)
            #pragma unroll
            for (int tn = 0; tn < 8; tn++) {
                tmax[tm * 2]     = fmaxf(tmax[tm * 2],     fmaxf(S[tm][tn][0], S[tm][tn][1]));
                tmax[tm * 2 + 1] = fmaxf(tmax[tm * 2 + 1], fmaxf(S[tm][tn][2], S[tm][tn][3]));
            }
        float al[4];
        #pragma unroll
        for (int i = 0; i < 4; i++) {
            tmax[i] = fmaxf(tmax[i], __shfl_xor_sync(0xffffffffu, tmax[i], 1));
            tmax[i] = fmaxf(tmax[i], __shfl_xor_sync(0xffffffffu, tmax[i], 2));
            const float mn = fmaxf(mv[i], tmax[i]);
            al[i] = ex2(mv[i] - mn);
            mv[i] = mn;
        }
        float rs[4] = { 0.f, 0.f, 0.f, 0.f };
        #pragma unroll
        for (int tm = 0; tm < 2; tm++)
            #pragma unroll
            for (int tn = 0; tn < 8; tn++) {
                S[tm][tn][0] = ex2(S[tm][tn][0] - mv[tm * 2]);
                S[tm][tn][1] = ex2(S[tm][tn][1] - mv[tm * 2]);
                S[tm][tn][2] = ex2(S[tm][tn][2] - mv[tm * 2 + 1]);
                S[tm][tn][3] = ex2(S[tm][tn][3] - mv[tm * 2 + 1]);
                rs[tm * 2]     += S[tm][tn][0] + S[tm][tn][1];
                rs[tm * 2 + 1] += S[tm][tn][2] + S[tm][tn][3];
            }
        #pragma unroll
        for (int i = 0; i < 4; i++) {
            rs[i] += __shfl_xor_sync(0xffffffffu, rs[i], 1);
            rs[i] += __shfl_xor_sync(0xffffffffu, rs[i], 2);
            lv[i] = lv[i] * al[i] + rs[i];
        }

        // rescale O, accumulate P @ V directly from S registers (RAW fp32 bits:
        // tf32 mma truncates to upper 19 bits -- no cvt on the critical chain)
        #pragma unroll
        for (int tm = 0; tm < 2; tm++)
            #pragma unroll
            for (int tn = 0; tn < 8; tn++) {
                O[tm][tn][0] *= al[tm * 2];     O[tm][tn][1] *= al[tm * 2];
                O[tm][tn][2] *= al[tm * 2 + 1]; O[tm][tn][3] *= al[tm * 2 + 1];
            }
        #pragma unroll
        for (int ks = 0; ks < 8; ks++) {
            uint32_t a[2][4];
            #pragma unroll
            for (int tm = 0; tm < 2; tm++) {
                a[tm][0] = __float_as_uint(S[tm][ks][0]);
                a[tm][1] = __float_as_uint(S[tm][ks][2]);
                a[tm][2] = __float_as_uint(S[tm][ks][1]);
                a[tm][3] = __float_as_uint(S[tm][ks][3]);
            }
            #pragma unroll
            for (int tn = 0; tn < 8; tn++) {
                uint32_t bb[2];
                bb[0] = Vs[(tn * 8 + g) * 68 + ks * 8 + q];
                bb[1] = Vs[(tn * 8 + g) * 68 + ks * 8 + q + 4];
                mma8(O[0][tn], a[0], bb);
                mma8(O[1][tn], a[1], bb);
            }
        }
        if (lane == 0) mb_arrive(ubar + 16 + b * 8);   // release stage b
    }

    if (!split) {
        // unsplit: normalize and write g_att (tf32-rounded for the out GEMM)
        #pragma unroll
        for (int tm = 0; tm < 2; tm++) {
            const int ra = r0 + tm * 16;
            const float i0 = 1.f / lv[tm * 2], i1 = 1.f / lv[tm * 2 + 1];
            #pragma unroll
            for (int tn = 0; tn < 8; tn++) {
                const int d = tn * 8 + 2 * q;
                uint2 v0 = { tf32r(O[tm][tn][0] * i0), tf32r(O[tm][tn][1] * i0) };
                uint2 v1 = { tf32r(O[tm][tn][2] * i1), tf32r(O[tm][tn][3] * i1) };
                *(uint2*)(g_att + (size_t)ra * CC + h * DH + d) = v0;
                *(uint2*)(g_att + (size_t)(ra + 8) * CC + h * DH + d) = v1;
            }
        }
    } else {
        // split: write unnormalized O + (m, l) to scratch (rows 0..3071 per head)
        const int sb = (qb - 8) * 128;
        float* poB = g_po + ((size_t)part * HH + h) * 3072 * 64;
        #pragma unroll
        for (int tm = 0; tm < 2; tm++) {
            const int lr = rb + tm * 16 + g;
            #pragma unroll
            for (int tn = 0; tn < 8; tn++) {
                const int d = tn * 8 + 2 * q;
                float2 v0 = { O[tm][tn][0], O[tm][tn][1] };
                float2 v1 = { O[tm][tn][2], O[tm][tn][3] };
                *(float2*)(poB + (size_t)(sb + lr) * 64 + d) = v0;
                *(float2*)(poB + (size_t)(sb + lr + 8) * 64 + d) = v1;
            }
            if (q == 0) {
                const size_t mi = ((size_t)part * HH + h) * 3072 + sb;
                g_pm[mi + lr]     = mv[tm * 2];     g_pl[mi + lr]     = lv[tm * 2];
                g_pm[mi + lr + 8] = mv[tm * 2 + 1]; g_pl[mi + lr + 8] = lv[tm * 2 + 1];
            }
        }
    }
}

// ---------------- merge split-K partials (token rows 1024..4095, 2-4 parts) ----------
__global__ __launch_bounds__(256) void merge_k()
{
    const int idx = blockIdx.x * 256 + threadIdx.x;   // 12 * 3072 * 16 = 589824
    const int d4  = (idx & 15) * 4;
    const int row = (idx >> 4) % 3072;
    const int h   = idx / (3072 * 16);

    const int qb = 8 + (row >> 7);
    const int np = (qb >= 24) ? 4 : (qb >= 16) ? 3 : 2;

    const size_t mi0 = (size_t)h * 3072 + row;
    float m = -1e30f;
    #pragma unroll
    for (int p = 0; p < 4; p++)
        if (p < np) m = fmaxf(m, g_pm[(size_t)p * HH * 3072 + mi0]);

    float den = 0.f;
    float4 acc = { 0.f, 0.f, 0.f, 0.f };
    #pragma unroll
    for (int p = 0; p < 4; p++) {
        if (p >= np) break;
        const size_t mi = (size_t)p * HH * 3072 + mi0;
        const float w = ex2(g_pm[mi] - m);
        den += g_pl[mi] * w;
        const float4 o = *(const float4*)(g_po + ((size_t)p * HH + h) * 3072 * 64
                                               + (size_t)row * 64 + d4);
        acc.x += o.x * w; acc.y += o.y * w; acc.z += o.z * w; acc.w += o.w * w;
    }
    const float inv = 1.f / den;
    uint4 r;
    r.x = tf32r(acc.x * inv); r.y = tf32r(acc.y * inv);
    r.z = tf32r(acc.z * inv); r.w = tf32r(acc.w * inv);

    const int tok = qb * 128 + (row & 127);
    *(uint4*)(g_att + (size_t)tok * CC + h * DH + d4) = r;
}

// ---------------- launcher ----------------
extern "C" void kernel_launch(void* const* d_in, const int* in_sizes, int n_in,
                              void* d_out, int out_size)
{
    const float* x  = (const float*)d_in[0];
    const float* wq = (const float*)d_in[1];
    const float* bq = (const float*)d_in[2];
    const float* wk = (const float*)d_in[3];
    const float* bk = (const float*)d_in[4];
    const float* wv = (const float*)d_in[5];
    const float* bv = (const float*)d_in[6];
    const float* wo = (const float*)d_in[7];
    const float* bo = (const float*)d_in[8];

    const int GSM  = 3 * GBUFSZ * 4;    // 110592 B (qkv, 3-stage 128x128)
    const int OSM  = 3 * OBUFSZ * 4;    // 82944 B  (out, 3-stage 128x64)
    const int ASM  = 26112 * 4;         // 104448 B
    cudaFuncSetAttribute(gemm_qkv, cudaFuncAttributeMaxDynamicSharedMemorySize, GSM);
    cudaFuncSetAttribute(gemm_out, cudaFuncAttributeMaxDynamicSharedMemorySize, OSM);
    cudaFuncSetAttribute(attn,     cudaFuncAttributeMaxDynamicSharedMemorySize, ASM);

    float* xt_dev;  cudaGetSymbolAddress((void**)&xt_dev,  g_xt);
    float* wt_dev;  cudaGetSymbolAddress((void**)&wt_dev,  g_wt);
    float* wot_dev; cudaGetSymbolAddress((void**)&wot_dev, g_wot);
    float* att_dev; cudaGetSymbolAddress((void**)&att_dev, g_att);

    prep<<<3648, 256>>>(x, wq, wk, wv, wo);
    gemm_qkv<<<dim3(32, 18), 256, GSM>>>(xt_dev, wt_dev, bq, bk, bv);
    attn<<<dim3(80, 12), 128, ASM>>>();
    merge_k<<<2304, 256>>>();
    gemm_out<<<dim3(32, 12), 128, OSM>>>(att_dev, wot_dev, bo, (float*)d_out);
}